// round 13
// baseline (speedup 1.0000x reference)
#include <cuda_runtime.h>
#include <cuda_fp16.h>
#include <math.h>
#include <stdint.h>

// Problem constants
#define NLAYER 4
#define HDIM   1024
#define NHEAD  16
#define HEADD  64
#define FFDIM  4096
#define BATCH  4
#define SEQ    1024
#define MTOK   (BATCH * SEQ)   // 4096 tokens

// ---------------------------------------------------------------------------
// Scratch (allocation-free: __device__ globals)
// ---------------------------------------------------------------------------
__device__ float g_h   [MTOK * HDIM];
__device__ __align__(16) __half g_xh   [MTOK * HDIM];
__device__ __align__(16) __half g_attnh[MTOK * HDIM];
__device__ __align__(16) __half g_fch  [MTOK * FFDIM];
// Per-head Q/K/V, layout [b*NH][S][64] half
__device__ __align__(16) __half g_qheads[MTOK * HDIM];
__device__ __align__(16) __half g_kheads[MTOK * HDIM];
__device__ __align__(16) __half g_vheads[MTOK * HDIM];
// Converted weights, layout [l][N][K] half
__device__ __align__(16) __half g_Wqkvh [NLAYER * 3 * HDIM * HDIM];
__device__ __align__(16) __half g_Woh   [NLAYER * HDIM * HDIM];
__device__ __align__(16) __half g_Wfch  [NLAYER * HDIM * FFDIM];
__device__ __align__(16) __half g_Wprojh[NLAYER * FFDIM * HDIM];

// ---------------------------------------------------------------------------
// PTX helpers
// ---------------------------------------------------------------------------
__device__ __forceinline__ uint32_t smem_u32(const void* p) {
    uint32_t a;
    asm("{ .reg .u64 t; cvta.to.shared.u64 t, %1; cvt.u32.u64 %0, t; }" : "=r"(a) : "l"(p));
    return a;
}
__device__ __forceinline__ void cp_async16(uint32_t s, const void* g) {
    asm volatile("cp.async.cg.shared.global [%0], [%1], 16;\n" :: "r"(s), "l"(g));
}
__device__ __forceinline__ void cp_commit() {
    asm volatile("cp.async.commit_group;\n" ::: "memory");
}
__device__ __forceinline__ void mma_f16(float* c, const uint32_t* a, const uint32_t* b) {
    asm volatile(
        "mma.sync.aligned.m16n8k16.row.col.f32.f16.f16.f32 "
        "{%0,%1,%2,%3}, {%4,%5,%6,%7}, {%8,%9}, {%0,%1,%2,%3};"
        : "+f"(c[0]), "+f"(c[1]), "+f"(c[2]), "+f"(c[3])
        : "r"(a[0]), "r"(a[1]), "r"(a[2]), "r"(a[3]), "r"(b[0]), "r"(b[1]));
}
__device__ __forceinline__ void mma_f16s(float* c, const uint32_t* a,
                                         uint32_t b0, uint32_t b1) {
    asm volatile(
        "mma.sync.aligned.m16n8k16.row.col.f32.f16.f16.f32 "
        "{%0,%1,%2,%3}, {%4,%5,%6,%7}, {%8,%9}, {%0,%1,%2,%3};"
        : "+f"(c[0]), "+f"(c[1]), "+f"(c[2]), "+f"(c[3])
        : "r"(a[0]), "r"(a[1]), "r"(a[2]), "r"(a[3]), "r"(b0), "r"(b1));
}
__device__ __forceinline__ void ldmx4(uint32_t* r, uint32_t addr) {
    asm volatile("ldmatrix.sync.aligned.m8n8.x4.shared.b16 {%0,%1,%2,%3}, [%4];"
        : "=r"(r[0]), "=r"(r[1]), "=r"(r[2]), "=r"(r[3]) : "r"(addr));
}
__device__ __forceinline__ void ldmx2(uint32_t* r, uint32_t addr) {
    asm volatile("ldmatrix.sync.aligned.m8n8.x2.shared.b16 {%0,%1}, [%2];"
        : "=r"(r[0]), "=r"(r[1]) : "r"(addr));
}
__device__ __forceinline__ void ldmx2t(uint32_t* r, uint32_t addr) {
    asm volatile("ldmatrix.sync.aligned.m8n8.x2.trans.shared.b16 {%0,%1}, [%2];"
        : "=r"(r[0]), "=r"(r[1]) : "r"(addr));
}

// ---------------------------------------------------------------------------
// fp16 mma GEMM config (R6 proven):
// CTA 128x128, 8 warps (warp tile 64x32), BK=64, 3-stage cp.async.
// R13 change: B fragments via paired ldmatrix.x4 (2 loads/ks instead of 4).
// ---------------------------------------------------------------------------
#define STAGES    3
#define AT_BYTES  16384
#define STAGE_SZ  32768
#define GEMM_SMEM (STAGES * STAGE_SZ)

#define GEMM_MAINLOOP(A, Bt, K)                                                  \
    const uint32_t sbase = smem_u32(smem);                                       \
    const int tid  = threadIdx.x;                                                \
    const int wid  = tid >> 5;                                                   \
    const int lane = tid & 31;                                                   \
    const int g    = lane >> 2;                                                  \
    const int t4   = lane & 3;                                                   \
    const int M0 = blockIdx.y * 128;                                             \
    const int N0 = blockIdx.x * 128;                                             \
    const int wm0 = (wid >> 2) * 64;                                             \
    const int wn0 = (wid & 3) * 32;                                              \
    const int iters = (K) >> 6;                                                  \
    const int a_lrow  = (lane & 7) + 8 * ((lane >> 3) & 1);                      \
    const int a_colhi = lane >> 4;                                               \
    const int a_xor   = a_lrow & 7;                                              \
    auto load_stage = [&](int s, int k0) {                                       \
        const uint32_t sA = sbase + s * STAGE_SZ;                                \
        const uint32_t sB = sA + AT_BYTES;                                       \
        _Pragma("unroll")                                                        \
        for (int i = 0; i < 4; i++) {                                            \
            const int c = tid + 256 * i;                                         \
            const int r = c >> 3, cc = c & 7;                                    \
            cp_async16(sA + (uint32_t)(r * 128 + ((cc ^ (r & 7)) * 16)),         \
                       (A) + (size_t)(M0 + r) * (K) + k0 + cc * 8);              \
        }                                                                        \
        _Pragma("unroll")                                                        \
        for (int i = 0; i < 4; i++) {                                            \
            const int c = tid + 256 * i;                                         \
            const int r = c >> 3, cc = c & 7;                                    \
            cp_async16(sB + (uint32_t)(r * 128 + ((cc ^ (r & 7)) * 16)),         \
                       (Bt) + (size_t)(N0 + r) * (K) + k0 + cc * 8);             \
        }                                                                        \
        cp_commit();                                                             \
    };                                                                           \
    float acc[4][4][4];                                                          \
    _Pragma("unroll")                                                            \
    for (int mf = 0; mf < 4; mf++)                                               \
        _Pragma("unroll")                                                        \
        for (int nf = 0; nf < 4; nf++)                                           \
            _Pragma("unroll")                                                    \
            for (int r = 0; r < 4; r++) acc[mf][nf][r] = 0.f;                    \
    load_stage(0, 0);                                                            \
    load_stage(1, 64);                                                           \
    for (int it = 0; it < iters; it++) {                                         \
        asm volatile("cp.async.wait_group 1;\n" ::: "memory");                   \
        __syncthreads();                                                         \
        if (it + 2 < iters) load_stage((it + 2) % STAGES, (it + 2) * 64);        \
        else                cp_commit();                                         \
        const uint32_t sA = sbase + (it % STAGES) * STAGE_SZ;                    \
        const uint32_t sB = sA + AT_BYTES;                                       \
        _Pragma("unroll")                                                        \
        for (int ks = 0; ks < 4; ks++) {                                         \
            const uint32_t chunk = (uint32_t)(((2 * ks + a_colhi) ^ a_xor) * 16);\
            uint32_t af[4][4], braw[2][4];                                       \
            _Pragma("unroll")                                                    \
            for (int mf = 0; mf < 4; mf++)                                       \
                ldmx4(af[mf],                                                    \
                      sA + (uint32_t)((wm0 + mf * 16 + a_lrow) * 128) + chunk);  \
            _Pragma("unroll")                                                    \
            for (int p = 0; p < 2; p++)                                          \
                ldmx4(braw[p],                                                   \
                      sB + (uint32_t)((wn0 + p * 16 + a_lrow) * 128) + chunk);   \
            _Pragma("unroll")                                                    \
            for (int mf = 0; mf < 4; mf++)                                       \
                _Pragma("unroll")                                                \
                for (int nf = 0; nf < 4; nf++) {                                 \
                    const int p = nf >> 1, o = nf & 1;                           \
                    mma_f16s(acc[mf][nf], af[mf], braw[p][o], braw[p][o + 2]);   \
                }                                                                \
        }                                                                        \
    }

// Generic epilogue GEMM. EPI: 0=bias->f32, 1=bias+res->f32, 2=bias+gelu->half
template <int EPI>
__global__ void __launch_bounds__(256, 2)
mma_gemm(const __half* __restrict__ A, const __half* __restrict__ Bt,
         const float* __restrict__ bias, const float* __restrict__ Res,
         void* __restrict__ Cout, int M, int N, int K) {
    extern __shared__ char smem[];
    GEMM_MAINLOOP(A, Bt, K)

    #pragma unroll
    for (int mf = 0; mf < 4; mf++) {
        #pragma unroll
        for (int nf = 0; nf < 4; nf++) {
            const int col  = N0 + wn0 + nf * 8 + t4 * 2;
            const int row0 = M0 + wm0 + mf * 16 + g;
            const float b0 = bias[col], b1 = bias[col + 1];
            #pragma unroll
            for (int half_i = 0; half_i < 2; half_i++) {
                const int row = row0 + half_i * 8;
                float v0 = acc[mf][nf][half_i * 2 + 0] + b0;
                float v1 = acc[mf][nf][half_i * 2 + 1] + b1;
                if (EPI == 1) {
                    const float2 rv = *(const float2*)(Res + (size_t)row * N + col);
                    v0 += rv.x; v1 += rv.y;
                }
                if (EPI == 2) {
                    float u0 = 0.7978845608028654f * (v0 + 0.044715f * v0 * v0 * v0);
                    float u1 = 0.7978845608028654f * (v1 + 0.044715f * v1 * v1 * v1);
                    v0 = 0.5f * v0 * (1.0f + tanhf(u0));
                    v1 = 0.5f * v1 * (1.0f + tanhf(u1));
                    *(__half2*)((__half*)Cout + (size_t)row * N + col) =
                        __floats2half2_rn(v0, v1);
                } else {
                    *(float2*)((float*)Cout + (size_t)row * N + col) =
                        make_float2(v0, v1);
                }
            }
        }
    }
}

// QKV GEMM with fused RoPE epilogue -> per-head half Q/K/V buffers.
__global__ void __launch_bounds__(256, 2)
mma_gemm_qkv(const __half* __restrict__ A, const __half* __restrict__ Bt,
             const float* __restrict__ bias,
             __half* __restrict__ Qh, __half* __restrict__ Kh,
             __half* __restrict__ Vh, int K) {
    extern __shared__ char smem[];
    GEMM_MAINLOOP(A, Bt, K)

    #pragma unroll
    for (int nf = 0; nf < 4; nf++) {
        const int col = N0 + wn0 + nf * 8 + t4 * 2;     // even column
        const int sec = col >> 10;                       // 0=q 1=k 2=v
        const int d   = col & 1023;
        const int hh  = d >> 6;
        const int dd  = d & 63;
        const int ip  = dd >> 1;                         // rope pair index
        const float invfreq = exp2f((float)ip * -0.41524101186092029f);
        const float b0 = bias[col], b1 = bias[col + 1];
        #pragma unroll
        for (int mf = 0; mf < 4; mf++) {
            #pragma unroll
            for (int half_i = 0; half_i < 2; half_i++) {
                const int row = M0 + wm0 + mf * 16 + g + half_i * 8;
                const int pos = row & (SEQ - 1);
                const int bb  = row >> 10;
                const size_t o = ((size_t)(bb * NHEAD + hh) * SEQ + pos) * 64 + dd;
                float v0 = acc[mf][nf][half_i * 2 + 0] + b0;
                float v1 = acc[mf][nf][half_i * 2 + 1] + b1;
                if (sec == 2) {
                    *(__half2*)&Vh[o] = __floats2half2_rn(v0, v1);
                } else {
                    float sn, cs;
                    sincosf((float)pos * invfreq, &sn, &cs);
                    const float r0 = v0 * cs - v1 * sn;
                    const float r1 = v1 * cs + v0 * sn;
                    if (sec == 0)
                        *(__half2*)&Qh[o] = __floats2half2_rn(r0 * 0.125f, r1 * 0.125f);
                    else
                        *(__half2*)&Kh[o] = __floats2half2_rn(r0, r1);
                }
            }
        }
    }
}

// ---------------------------------------------------------------------------
// Weight convert + transpose: W[l][K][N] fp32 -> Wh[l][N][K] half.
// Tile 64(k) x 32(n). Coalesced fp32 reads; contiguous half2 writes.
// ---------------------------------------------------------------------------
__global__ void convert_w(const float* __restrict__ W, __half* __restrict__ Wh,
                          int K, int N) {
    __shared__ float t[64][33];
    const int l = blockIdx.z;
    const float* Wl = W + (size_t)l * K * N;
    __half* Wo = Wh + (size_t)l * K * N;
    const int n0 = blockIdx.x * 32, k0 = blockIdx.y * 64;
    const int tx = threadIdx.x, ty = threadIdx.y;   // (32, 8)
    #pragma unroll
    for (int i = 0; i < 64; i += 8)
        t[ty + i][tx] = Wl[(size_t)(k0 + ty + i) * N + n0 + tx];
    __syncthreads();
    #pragma unroll
    for (int i = 0; i < 32; i += 8) {
        const int n = i + ty;
        const __half2 hv = __floats2half2_rn(t[2 * tx][n], t[2 * tx + 1][n]);
        *(__half2*)&Wo[(size_t)(n0 + n) * K + k0 + 2 * tx] = hv;
    }
}

// ---------------------------------------------------------------------------
// fp16 tensor-core flash attention (causal), heavy-first CTA order.
// CTA = (qtile 64 rows, head*batch), 128 threads (4 warps x 16 q rows).
// ---------------------------------------------------------------------------
#define AQ_OFF 0
#define AK_OFF 8192
#define AK_SZ  8192
#define AV_OFF 24576
#define AV_SZ  8192
#define AP_OFF 40960
#define AP_SZ  2048
#define ATTN_SMEM 49152

__global__ void __launch_bounds__(128)
mma_attn(const __half* __restrict__ Qh, const __half* __restrict__ Kh,
         const __half* __restrict__ Vh, __half* __restrict__ out) {
    extern __shared__ char smc[];
    const uint32_t sbase = smem_u32(smc);
    const int tid = threadIdx.x;
    const int wid = tid >> 5;
    const int lane = tid & 31;
    const int g = lane >> 2;
    const int t4 = lane & 3;

    const int qt = gridDim.x - 1 - blockIdx.x;   // heavy-first
    const int hb = blockIdx.y;
    const int q0 = qt * 64;
    const int ntiles = qt + 1;
    const size_t headbase = (size_t)hb * SEQ * 64;

    const int a_lrow  = (lane & 7) + 8 * ((lane >> 3) & 1);
    const int a_colhi = lane >> 4;
    const int a_xor   = a_lrow & 7;
    const int b_lrow  = lane & 7;
    const int b_chi   = (lane >> 3) & 1;
    const int vl      = lane & 15;

    auto load_tile = [&](uint32_t dst, const __half* src) {
        #pragma unroll
        for (int i = 0; i < 4; i++) {
            const int c = tid + 128 * i;
            const int r = c >> 3, ch = c & 7;
            cp_async16(dst + (uint32_t)(r * 128 + ((ch ^ (r & 7)) * 16)),
                       src + r * 64 + ch * 8);
        }
    };

    load_tile(sbase + AQ_OFF, Qh + headbase + (size_t)q0 * 64);
    load_tile(sbase + AK_OFF, Kh + headbase);
    load_tile(sbase + AV_OFF, Vh + headbase);
    cp_commit();

    float oacc[8][4];
    #pragma unroll
    for (int nf = 0; nf < 8; nf++)
        #pragma unroll
        for (int r = 0; r < 4; r++) oacc[nf][r] = 0.f;
    float m0 = -1e30f, m1 = -1e30f, l0 = 0.f, l1 = 0.f;

    const int qr0 = q0 + 16 * wid + g;

    for (int t = 0; t < ntiles; t++) {
        asm volatile("cp.async.wait_group 0;\n" ::: "memory");
        __syncthreads();

        if (t + 1 < ntiles) {
            const size_t kvoff = headbase + (size_t)(t + 1) * 64 * 64;
            load_tile(sbase + AK_OFF + ((t + 1) & 1) * AK_SZ, Kh + kvoff);
            load_tile(sbase + AV_OFF + ((t + 1) & 1) * AV_SZ, Vh + kvoff);
            cp_commit();
        }

        const uint32_t Ks = sbase + AK_OFF + (t & 1) * AK_SZ;
        const uint32_t Vs = sbase + AV_OFF + (t & 1) * AV_SZ;
        const uint32_t Qs = sbase + AQ_OFF;
        const uint32_t Pw = sbase + AP_OFF + wid * AP_SZ;

        float sacc[8][4];
        #pragma unroll
        for (int nf = 0; nf < 8; nf++)
            #pragma unroll
            for (int r = 0; r < 4; r++) sacc[nf][r] = 0.f;

        #pragma unroll
        for (int ks = 0; ks < 4; ks++) {
            uint32_t af[4];
            ldmx4(af, Qs + (uint32_t)((16 * wid + a_lrow) * 128
                                      + (((2 * ks + a_colhi) ^ a_xor) * 16)));
            #pragma unroll
            for (int nf = 0; nf < 8; nf++) {
                uint32_t bf[2];
                ldmx2(bf, Ks + (uint32_t)((nf * 8 + b_lrow) * 128
                                          + (((2 * ks + b_chi) ^ (b_lrow & 7)) * 16)));
                mma_f16(sacc[nf], af, bf);
            }
        }

        const bool diag = (t == ntiles - 1);
        float mx0 = -1e30f, mx1 = -1e30f;
        #pragma unroll
        for (int nf = 0; nf < 8; nf++) {
            if (diag) {
                const int j = t * 64 + 8 * nf + 2 * t4;
                if (j     > qr0)     sacc[nf][0] = -1e30f;
                if (j + 1 > qr0)     sacc[nf][1] = -1e30f;
                if (j     > qr0 + 8) sacc[nf][2] = -1e30f;
                if (j + 1 > qr0 + 8) sacc[nf][3] = -1e30f;
            }
            mx0 = fmaxf(mx0, fmaxf(sacc[nf][0], sacc[nf][1]));
            mx1 = fmaxf(mx1, fmaxf(sacc[nf][2], sacc[nf][3]));
        }
        mx0 = fmaxf(mx0, __shfl_xor_sync(0xffffffffu, mx0, 1));
        mx0 = fmaxf(mx0, __shfl_xor_sync(0xffffffffu, mx0, 2));
        mx1 = fmaxf(mx1, __shfl_xor_sync(0xffffffffu, mx1, 1));
        mx1 = fmaxf(mx1, __shfl_xor_sync(0xffffffffu, mx1, 2));

        const float mn0 = fmaxf(m0, mx0);
        const float mn1 = fmaxf(m1, mx1);
        const float c0 = __expf(m0 - mn0);
        const float c1 = __expf(m1 - mn1);
        float sum0 = 0.f, sum1 = 0.f;
        #pragma unroll
        for (int nf = 0; nf < 8; nf++) {
            sacc[nf][0] = __expf(sacc[nf][0] - mn0);
            sacc[nf][1] = __expf(sacc[nf][1] - mn0);
            sacc[nf][2] = __expf(sacc[nf][2] - mn1);
            sacc[nf][3] = __expf(sacc[nf][3] - mn1);
            sum0 += sacc[nf][0] + sacc[nf][1];
            sum1 += sacc[nf][2] + sacc[nf][3];
        }
        sum0 += __shfl_xor_sync(0xffffffffu, sum0, 1);
        sum0 += __shfl_xor_sync(0xffffffffu, sum0, 2);
        sum1 += __shfl_xor_sync(0xffffffffu, sum1, 1);
        sum1 += __shfl_xor_sync(0xffffffffu, sum1, 2);
        l0 = l0 * c0 + sum0;
        l1 = l1 * c1 + sum1;
        m0 = mn0; m1 = mn1;

        #pragma unroll
        for (int nf = 0; nf < 8; nf++) {
            oacc[nf][0] *= c0; oacc[nf][1] *= c0;
            oacc[nf][2] *= c1; oacc[nf][3] *= c1;
            const uint32_t p0 = Pw + (uint32_t)(g * 128 + ((nf ^ (g & 7)) * 16) + t4 * 4);
            const uint32_t p1 = Pw + (uint32_t)((g + 8) * 128 + ((nf ^ ((g + 8) & 7)) * 16) + t4 * 4);
            *(__half2*)(smc + (p0 - sbase)) = __floats2half2_rn(sacc[nf][0], sacc[nf][1]);
            *(__half2*)(smc + (p1 - sbase)) = __floats2half2_rn(sacc[nf][2], sacc[nf][3]);
        }
        __syncwarp();

        #pragma unroll
        for (int ks = 0; ks < 4; ks++) {
            uint32_t af[4];
            ldmx4(af, Pw + (uint32_t)(a_lrow * 128
                                      + (((2 * ks + a_colhi) ^ a_xor) * 16)));
            const int vrow = 16 * ks + vl;
            #pragma unroll
            for (int nf = 0; nf < 8; nf++) {
                uint32_t bf[2];
                ldmx2t(bf, Vs + (uint32_t)(vrow * 128 + ((nf ^ (vrow & 7)) * 16)));
                mma_f16(oacc[nf], af, bf);
            }
        }
    }

    const float inv0 = 1.0f / l0;
    const float inv1 = 1.0f / l1;
    const int h = hb & (NHEAD - 1);
    const int b = hb >> 4;
    const size_t row0 = (size_t)b * SEQ + q0 + 16 * wid + g;
    #pragma unroll
    for (int nf = 0; nf < 8; nf++) {
        const int col = h * 64 + 8 * nf + 2 * t4;
        *(__half2*)&out[row0 * HDIM + col] =
            __floats2half2_rn(oacc[nf][0] * inv0, oacc[nf][1] * inv0);
        *(__half2*)&out[(row0 + 8) * HDIM + col] =
            __floats2half2_rn(oacc[nf][2] * inv1, oacc[nf][3] * inv1);
    }
}

// ---------------------------------------------------------------------------
// LayerNorm: one warp per row, one-pass moments.
// ---------------------------------------------------------------------------
template <int HALF_OUT>
__global__ void __launch_bounds__(256)
ln_kernel(const float* __restrict__ x, const float* __restrict__ gamma,
          const float* __restrict__ beta, void* __restrict__ yv) {
    const int warp = threadIdx.x >> 5;
    const int lane = threadIdx.x & 31;
    const int row = blockIdx.x * 8 + warp;
    const float* xr = x + (size_t)row * HDIM;

    float4 v[8];
    float s = 0.f, s2 = 0.f;
    #pragma unroll
    for (int j = 0; j < 8; j++) {
        v[j] = *(const float4*)(xr + lane * 4 + j * 128);
        s  += v[j].x + v[j].y + v[j].z + v[j].w;
        s2 += v[j].x * v[j].x + v[j].y * v[j].y
            + v[j].z * v[j].z + v[j].w * v[j].w;
    }
    #pragma unroll
    for (int off = 16; off; off >>= 1) {
        s  += __shfl_xor_sync(0xffffffffu, s,  off);
        s2 += __shfl_xor_sync(0xffffffffu, s2, off);
    }
    const float mean = s * (1.0f / HDIM);
    const float var  = s2 * (1.0f / HDIM) - mean * mean;
    const float rs   = rsqrtf(var + 1e-5f);

    #pragma unroll
    for (int j = 0; j < 8; j++) {
        const int ci = lane * 4 + j * 128;
        const float4 gv = *(const float4*)(gamma + ci);
        const float4 bv = *(const float4*)(beta + ci);
        const float o0 = (v[j].x - mean) * rs * gv.x + bv.x;
        const float o1 = (v[j].y - mean) * rs * gv.y + bv.y;
        const float o2 = (v[j].z - mean) * rs * gv.z + bv.z;
        const float o3 = (v[j].w - mean) * rs * gv.w + bv.w;
        if (HALF_OUT) {
            __half2 h01 = __floats2half2_rn(o0, o1);
            __half2 h23 = __floats2half2_rn(o2, o3);
            uint2 pk;
            pk.x = *(uint32_t*)&h01;
            pk.y = *(uint32_t*)&h23;
            *(uint2*)((__half*)yv + (size_t)row * HDIM + ci) = pk;
        } else {
            *(float4*)((float*)yv + (size_t)row * HDIM + ci) =
                make_float4(o0, o1, o2, o3);
        }
    }
}

// ---------------------------------------------------------------------------
// Launch
// ---------------------------------------------------------------------------
extern "C" void kernel_launch(void* const* d_in, const int* in_sizes, int n_in,
                              void* d_out, int out_size) {
    const float* embeds = (const float*)d_in[0];
    const float* Wqkv  = (const float*)d_in[2];
    const float* bqkv  = (const float*)d_in[3];
    const float* Wo    = (const float*)d_in[4];
    const float* bo    = (const float*)d_in[5];
    const float* ln1g  = (const float*)d_in[6];
    const float* ln1b  = (const float*)d_in[7];
    const float* ln2g  = (const float*)d_in[8];
    const float* ln2b  = (const float*)d_in[9];
    const float* Wfc   = (const float*)d_in[10];
    const float* bfc   = (const float*)d_in[11];
    const float* Wproj = (const float*)d_in[12];
    const float* bproj = (const float*)d_in[13];
    const float* lnfg  = (const float*)d_in[14];
    const float* lnfb  = (const float*)d_in[15];

    float *h;
    __half *xh, *attnh, *fch, *qh, *kh, *vh, *Wqkvh, *Woh, *Wfch, *Wprojh;
    cudaGetSymbolAddress((void**)&h,      g_h);
    cudaGetSymbolAddress((void**)&xh,     g_xh);
    cudaGetSymbolAddress((void**)&attnh,  g_attnh);
    cudaGetSymbolAddress((void**)&fch,    g_fch);
    cudaGetSymbolAddress((void**)&qh,     g_qheads);
    cudaGetSymbolAddress((void**)&kh,     g_kheads);
    cudaGetSymbolAddress((void**)&vh,     g_vheads);
    cudaGetSymbolAddress((void**)&Wqkvh,  g_Wqkvh);
    cudaGetSymbolAddress((void**)&Woh,    g_Woh);
    cudaGetSymbolAddress((void**)&Wfch,   g_Wfch);
    cudaGetSymbolAddress((void**)&Wprojh, g_Wprojh);

    cudaFuncSetAttribute(mma_gemm<0>, cudaFuncAttributeMaxDynamicSharedMemorySize, GEMM_SMEM);
    cudaFuncSetAttribute(mma_gemm<1>, cudaFuncAttributeMaxDynamicSharedMemorySize, GEMM_SMEM);
    cudaFuncSetAttribute(mma_gemm<2>, cudaFuncAttributeMaxDynamicSharedMemorySize, GEMM_SMEM);
    cudaFuncSetAttribute(mma_gemm_qkv, cudaFuncAttributeMaxDynamicSharedMemorySize, GEMM_SMEM);
    cudaFuncSetAttribute(mma_attn,     cudaFuncAttributeMaxDynamicSharedMemorySize, ATTN_SMEM);

    convert_w<<<dim3(3 * HDIM / 32, HDIM / 64, NLAYER), dim3(32, 8)>>>(Wqkv, Wqkvh, HDIM, 3 * HDIM);
    convert_w<<<dim3(HDIM / 32, HDIM / 64, NLAYER), dim3(32, 8)>>>(Wo, Woh, HDIM, HDIM);
    convert_w<<<dim3(FFDIM / 32, HDIM / 64, NLAYER), dim3(32, 8)>>>(Wfc, Wfch, HDIM, FFDIM);
    convert_w<<<dim3(HDIM / 32, FFDIM / 64, NLAYER), dim3(32, 8)>>>(Wproj, Wprojh, FFDIM, HDIM);

    for (int l = 0; l < NLAYER; l++) {
        const float* hin = (l == 0) ? embeds : h;
        ln_kernel<1><<<MTOK / 8, 256>>>(hin, ln1g + l * HDIM, ln1b + l * HDIM, xh);
        mma_gemm_qkv<<<dim3(3 * HDIM / 128, MTOK / 128), 256, GEMM_SMEM>>>(
            xh, Wqkvh + (size_t)l * HDIM * 3 * HDIM, bqkv + (size_t)l * 3 * HDIM,
            qh, kh, vh, HDIM);
        mma_attn<<<dim3(SEQ / 64, BATCH * NHEAD), 128, ATTN_SMEM>>>(qh, kh, vh, attnh);
        mma_gemm<1><<<dim3(HDIM / 128, MTOK / 128), 256, GEMM_SMEM>>>(
            attnh, Woh + (size_t)l * HDIM * HDIM, bo + (size_t)l * HDIM,
            hin, h, MTOK, HDIM, HDIM);
        ln_kernel<1><<<MTOK / 8, 256>>>(h, ln2g + l * HDIM, ln2b + l * HDIM, xh);
        mma_gemm<2><<<dim3(FFDIM / 128, MTOK / 128), 256, GEMM_SMEM>>>(
            xh, Wfch + (size_t)l * HDIM * FFDIM, bfc + (size_t)l * FFDIM,
            nullptr, fch, MTOK, FFDIM, HDIM);
        mma_gemm<1><<<dim3(HDIM / 128, MTOK / 128), 256, GEMM_SMEM>>>(
            fch, Wprojh + (size_t)l * FFDIM * HDIM, bproj + (size_t)l * HDIM,
            h, h, MTOK, HDIM, FFDIM);
    }
    ln_kernel<0><<<MTOK / 8, 256>>>(h, lnfg, lnfb, d_out);
}

// round 14
// speedup vs baseline: 1.0741x; 1.0741x over previous
#include <cuda_runtime.h>
#include <cuda_fp16.h>
#include <math.h>
#include <stdint.h>

// Problem constants
#define NLAYER 4
#define HDIM   1024
#define NHEAD  16
#define HEADD  64
#define FFDIM  4096
#define BATCH  4
#define SEQ    1024
#define MTOK   (BATCH * SEQ)   // 4096 tokens

// ---------------------------------------------------------------------------
// Scratch (allocation-free: __device__ globals)
// ---------------------------------------------------------------------------
__device__ float g_h   [MTOK * HDIM];
__device__ __align__(16) __half g_xh   [MTOK * HDIM];
__device__ __align__(16) __half g_attnh[MTOK * HDIM];
__device__ __align__(16) __half g_fch  [MTOK * FFDIM];
// Per-head Q/K/V, layout [b*NH][S][64] half
__device__ __align__(16) __half g_qheads[MTOK * HDIM];
__device__ __align__(16) __half g_kheads[MTOK * HDIM];
__device__ __align__(16) __half g_vheads[MTOK * HDIM];
// Converted weights, layout [l][N][K] half
__device__ __align__(16) __half g_Wqkvh [NLAYER * 3 * HDIM * HDIM];
__device__ __align__(16) __half g_Woh   [NLAYER * HDIM * HDIM];
__device__ __align__(16) __half g_Wfch  [NLAYER * HDIM * FFDIM];
__device__ __align__(16) __half g_Wprojh[NLAYER * FFDIM * HDIM];

// ---------------------------------------------------------------------------
// PTX helpers
// ---------------------------------------------------------------------------
__device__ __forceinline__ uint32_t smem_u32(const void* p) {
    uint32_t a;
    asm("{ .reg .u64 t; cvta.to.shared.u64 t, %1; cvt.u32.u64 %0, t; }" : "=r"(a) : "l"(p));
    return a;
}
__device__ __forceinline__ void cp_async16(uint32_t s, const void* g) {
    asm volatile("cp.async.cg.shared.global [%0], [%1], 16;\n" :: "r"(s), "l"(g));
}
__device__ __forceinline__ void cp_commit() {
    asm volatile("cp.async.commit_group;\n" ::: "memory");
}
__device__ __forceinline__ void mma_f16(float* c, const uint32_t* a, const uint32_t* b) {
    asm volatile(
        "mma.sync.aligned.m16n8k16.row.col.f32.f16.f16.f32 "
        "{%0,%1,%2,%3}, {%4,%5,%6,%7}, {%8,%9}, {%0,%1,%2,%3};"
        : "+f"(c[0]), "+f"(c[1]), "+f"(c[2]), "+f"(c[3])
        : "r"(a[0]), "r"(a[1]), "r"(a[2]), "r"(a[3]), "r"(b[0]), "r"(b[1]));
}
__device__ __forceinline__ void ldmx4(uint32_t* r, uint32_t addr) {
    asm volatile("ldmatrix.sync.aligned.m8n8.x4.shared.b16 {%0,%1,%2,%3}, [%4];"
        : "=r"(r[0]), "=r"(r[1]), "=r"(r[2]), "=r"(r[3]) : "r"(addr));
}
__device__ __forceinline__ void ldmx2(uint32_t* r, uint32_t addr) {
    asm volatile("ldmatrix.sync.aligned.m8n8.x2.shared.b16 {%0,%1}, [%2];"
        : "=r"(r[0]), "=r"(r[1]) : "r"(addr));
}
__device__ __forceinline__ void ldmx2t(uint32_t* r, uint32_t addr) {
    asm volatile("ldmatrix.sync.aligned.m8n8.x2.trans.shared.b16 {%0,%1}, [%2];"
        : "=r"(r[0]), "=r"(r[1]) : "r"(addr));
}

// ---------------------------------------------------------------------------
// fp16 mma GEMM config (R6/R12 proven — FROZEN):
// CTA 128x128, 8 warps (warp tile 64x32), BK=64, 3-stage cp.async.
// ---------------------------------------------------------------------------
#define STAGES    3
#define AT_BYTES  16384
#define STAGE_SZ  32768
#define GEMM_SMEM (STAGES * STAGE_SZ)

#define GEMM_MAINLOOP(A, Bt, K)                                                  \
    const uint32_t sbase = smem_u32(smem);                                       \
    const int tid  = threadIdx.x;                                                \
    const int wid  = tid >> 5;                                                   \
    const int lane = tid & 31;                                                   \
    const int g    = lane >> 2;                                                  \
    const int t4   = lane & 3;                                                   \
    const int M0 = blockIdx.y * 128;                                             \
    const int N0 = blockIdx.x * 128;                                             \
    const int wm0 = (wid >> 2) * 64;                                             \
    const int wn0 = (wid & 3) * 32;                                              \
    const int iters = (K) >> 6;                                                  \
    const int a_lrow  = (lane & 7) + 8 * ((lane >> 3) & 1);                      \
    const int a_colhi = lane >> 4;                                               \
    const int a_xor   = a_lrow & 7;                                              \
    const int b_lrow  = lane & 7;                                                \
    const int b_chi   = (lane >> 3) & 1;                                         \
    auto load_stage = [&](int s, int k0) {                                       \
        const uint32_t sA = sbase + s * STAGE_SZ;                                \
        const uint32_t sB = sA + AT_BYTES;                                       \
        _Pragma("unroll")                                                        \
        for (int i = 0; i < 4; i++) {                                            \
            const int c = tid + 256 * i;                                         \
            const int r = c >> 3, cc = c & 7;                                    \
            cp_async16(sA + (uint32_t)(r * 128 + ((cc ^ (r & 7)) * 16)),         \
                       (A) + (size_t)(M0 + r) * (K) + k0 + cc * 8);              \
        }                                                                        \
        _Pragma("unroll")                                                        \
        for (int i = 0; i < 4; i++) {                                            \
            const int c = tid + 256 * i;                                         \
            const int r = c >> 3, cc = c & 7;                                    \
            cp_async16(sB + (uint32_t)(r * 128 + ((cc ^ (r & 7)) * 16)),         \
                       (Bt) + (size_t)(N0 + r) * (K) + k0 + cc * 8);             \
        }                                                                        \
        cp_commit();                                                             \
    };                                                                           \
    float acc[4][4][4];                                                          \
    _Pragma("unroll")                                                            \
    for (int mf = 0; mf < 4; mf++)                                               \
        _Pragma("unroll")                                                        \
        for (int nf = 0; nf < 4; nf++)                                           \
            _Pragma("unroll")                                                    \
            for (int r = 0; r < 4; r++) acc[mf][nf][r] = 0.f;                    \
    load_stage(0, 0);                                                            \
    load_stage(1, 64);                                                           \
    for (int it = 0; it < iters; it++) {                                         \
        asm volatile("cp.async.wait_group 1;\n" ::: "memory");                   \
        __syncthreads();                                                         \
        if (it + 2 < iters) load_stage((it + 2) % STAGES, (it + 2) * 64);        \
        else                cp_commit();                                         \
        const uint32_t sA = sbase + (it % STAGES) * STAGE_SZ;                    \
        const uint32_t sB = sA + AT_BYTES;                                       \
        _Pragma("unroll")                                                        \
        for (int ks = 0; ks < 4; ks++) {                                         \
            uint32_t af[4][4], bf[4][2];                                         \
            _Pragma("unroll")                                                    \
            for (int mf = 0; mf < 4; mf++) {                                     \
                const uint32_t adr = sA                                          \
                    + (uint32_t)((wm0 + mf * 16 + a_lrow) * 128                  \
                                 + (((2 * ks + a_colhi) ^ a_xor) * 16));         \
                ldmx4(af[mf], adr);                                              \
            }                                                                    \
            _Pragma("unroll")                                                    \
            for (int nf = 0; nf < 4; nf++) {                                     \
                const uint32_t badr = sB                                         \
                    + (uint32_t)((wn0 + nf * 8 + b_lrow) * 128                   \
                                 + (((2 * ks + b_chi) ^ (b_lrow & 7)) * 16));    \
                ldmx2(bf[nf], badr);                                             \
            }                                                                    \
            _Pragma("unroll")                                                    \
            for (int mf = 0; mf < 4; mf++)                                       \
                _Pragma("unroll")                                                \
                for (int nf = 0; nf < 4; nf++)                                   \
                    mma_f16(acc[mf][nf], af[mf], bf[nf]);                        \
        }                                                                        \
    }

// Generic epilogue GEMM. EPI: 0=bias->f32, 1=bias+res->f32, 2=bias+gelu->half
template <int EPI>
__global__ void __launch_bounds__(256, 2)
mma_gemm(const __half* __restrict__ A, const __half* __restrict__ Bt,
         const float* __restrict__ bias, const float* __restrict__ Res,
         void* __restrict__ Cout, int M, int N, int K) {
    extern __shared__ char smem[];
    GEMM_MAINLOOP(A, Bt, K)

    #pragma unroll
    for (int mf = 0; mf < 4; mf++) {
        #pragma unroll
        for (int nf = 0; nf < 4; nf++) {
            const int col  = N0 + wn0 + nf * 8 + t4 * 2;
            const int row0 = M0 + wm0 + mf * 16 + g;
            const float b0 = bias[col], b1 = bias[col + 1];
            #pragma unroll
            for (int half_i = 0; half_i < 2; half_i++) {
                const int row = row0 + half_i * 8;
                float v0 = acc[mf][nf][half_i * 2 + 0] + b0;
                float v1 = acc[mf][nf][half_i * 2 + 1] + b1;
                if (EPI == 1) {
                    const float2 rv = *(const float2*)(Res + (size_t)row * N + col);
                    v0 += rv.x; v1 += rv.y;
                }
                if (EPI == 2) {
                    float u0 = 0.7978845608028654f * (v0 + 0.044715f * v0 * v0 * v0);
                    float u1 = 0.7978845608028654f * (v1 + 0.044715f * v1 * v1 * v1);
                    v0 = 0.5f * v0 * (1.0f + tanhf(u0));
                    v1 = 0.5f * v1 * (1.0f + tanhf(u1));
                    *(__half2*)((__half*)Cout + (size_t)row * N + col) =
                        __floats2half2_rn(v0, v1);
                } else {
                    *(float2*)((float*)Cout + (size_t)row * N + col) =
                        make_float2(v0, v1);
                }
            }
        }
    }
}

// QKV GEMM with fused RoPE epilogue -> per-head half Q/K/V buffers.
__global__ void __launch_bounds__(256, 2)
mma_gemm_qkv(const __half* __restrict__ A, const __half* __restrict__ Bt,
             const float* __restrict__ bias,
             __half* __restrict__ Qh, __half* __restrict__ Kh,
             __half* __restrict__ Vh, int K) {
    extern __shared__ char smem[];
    GEMM_MAINLOOP(A, Bt, K)

    #pragma unroll
    for (int nf = 0; nf < 4; nf++) {
        const int col = N0 + wn0 + nf * 8 + t4 * 2;     // even column
        const int sec = col >> 10;                       // 0=q 1=k 2=v
        const int d   = col & 1023;
        const int hh  = d >> 6;
        const int dd  = d & 63;
        const int ip  = dd >> 1;                         // rope pair index
        const float invfreq = exp2f((float)ip * -0.41524101186092029f);
        const float b0 = bias[col], b1 = bias[col + 1];
        #pragma unroll
        for (int mf = 0; mf < 4; mf++) {
            #pragma unroll
            for (int half_i = 0; half_i < 2; half_i++) {
                const int row = M0 + wm0 + mf * 16 + g + half_i * 8;
                const int pos = row & (SEQ - 1);
                const int bb  = row >> 10;
                const size_t o = ((size_t)(bb * NHEAD + hh) * SEQ + pos) * 64 + dd;
                float v0 = acc[mf][nf][half_i * 2 + 0] + b0;
                float v1 = acc[mf][nf][half_i * 2 + 1] + b1;
                if (sec == 2) {
                    *(__half2*)&Vh[o] = __floats2half2_rn(v0, v1);
                } else {
                    float sn, cs;
                    sincosf((float)pos * invfreq, &sn, &cs);
                    const float r0 = v0 * cs - v1 * sn;
                    const float r1 = v1 * cs + v0 * sn;
                    if (sec == 0)
                        *(__half2*)&Qh[o] = __floats2half2_rn(r0 * 0.125f, r1 * 0.125f);
                    else
                        *(__half2*)&Kh[o] = __floats2half2_rn(r0, r1);
                }
            }
        }
    }
}

// ---------------------------------------------------------------------------
// Weight convert + transpose v2: W[l][K][N] fp32 -> Wh[l][N][K] half.
// Tile 64(k) x 64(n); float2 reads (256B/warp), contiguous half2 writes.
// ---------------------------------------------------------------------------
__global__ void convert_w(const float* __restrict__ W, __half* __restrict__ Wh,
                          int K, int N) {
    __shared__ float t[64][65];
    const int l = blockIdx.z;
    const float* Wl = W + (size_t)l * K * N;
    __half* Wo = Wh + (size_t)l * K * N;
    const int n0 = blockIdx.x * 64, k0 = blockIdx.y * 64;
    const int tx = threadIdx.x, ty = threadIdx.y;   // (32, 8)
    #pragma unroll
    for (int i = 0; i < 64; i += 8) {
        const float2 rv = *(const float2*)(Wl + (size_t)(k0 + ty + i) * N + n0 + 2 * tx);
        t[ty + i][2 * tx]     = rv.x;
        t[ty + i][2 * tx + 1] = rv.y;
    }
    __syncthreads();
    #pragma unroll
    for (int i = 0; i < 64; i += 8) {
        const int n = i + ty;
        const __half2 hv = __floats2half2_rn(t[2 * tx][n], t[2 * tx + 1][n]);
        *(__half2*)&Wo[(size_t)(n0 + n) * K + k0 + 2 * tx] = hv;
    }
}

// ---------------------------------------------------------------------------
// fp16 tensor-core flash attention (causal), heavy-first CTA order (R12).
// CTA = (qtile 64 rows, head*batch), 128 threads (4 warps x 16 q rows).
// ---------------------------------------------------------------------------
#define AQ_OFF 0
#define AK_OFF 8192
#define AK_SZ  8192
#define AV_OFF 24576
#define AV_SZ  8192
#define AP_OFF 40960
#define AP_SZ  2048
#define ATTN_SMEM 49152

__global__ void __launch_bounds__(128)
mma_attn(const __half* __restrict__ Qh, const __half* __restrict__ Kh,
         const __half* __restrict__ Vh, __half* __restrict__ out) {
    extern __shared__ char smc[];
    const uint32_t sbase = smem_u32(smc);
    const int tid = threadIdx.x;
    const int wid = tid >> 5;
    const int lane = tid & 31;
    const int g = lane >> 2;
    const int t4 = lane & 3;

    const int qt = gridDim.x - 1 - blockIdx.x;   // heavy-first
    const int hb = blockIdx.y;
    const int q0 = qt * 64;
    const int ntiles = qt + 1;
    const size_t headbase = (size_t)hb * SEQ * 64;

    const int a_lrow  = (lane & 7) + 8 * ((lane >> 3) & 1);
    const int a_colhi = lane >> 4;
    const int a_xor   = a_lrow & 7;
    const int b_lrow  = lane & 7;
    const int b_chi   = (lane >> 3) & 1;
    const int vl      = lane & 15;

    auto load_tile = [&](uint32_t dst, const __half* src) {
        #pragma unroll
        for (int i = 0; i < 4; i++) {
            const int c = tid + 128 * i;
            const int r = c >> 3, ch = c & 7;
            cp_async16(dst + (uint32_t)(r * 128 + ((ch ^ (r & 7)) * 16)),
                       src + r * 64 + ch * 8);
        }
    };

    load_tile(sbase + AQ_OFF, Qh + headbase + (size_t)q0 * 64);
    load_tile(sbase + AK_OFF, Kh + headbase);
    load_tile(sbase + AV_OFF, Vh + headbase);
    cp_commit();

    float oacc[8][4];
    #pragma unroll
    for (int nf = 0; nf < 8; nf++)
        #pragma unroll
        for (int r = 0; r < 4; r++) oacc[nf][r] = 0.f;
    float m0 = -1e30f, m1 = -1e30f, l0 = 0.f, l1 = 0.f;

    const int qr0 = q0 + 16 * wid + g;

    for (int t = 0; t < ntiles; t++) {
        asm volatile("cp.async.wait_group 0;\n" ::: "memory");
        __syncthreads();

        if (t + 1 < ntiles) {
            const size_t kvoff = headbase + (size_t)(t + 1) * 64 * 64;
            load_tile(sbase + AK_OFF + ((t + 1) & 1) * AK_SZ, Kh + kvoff);
            load_tile(sbase + AV_OFF + ((t + 1) & 1) * AV_SZ, Vh + kvoff);
            cp_commit();
        }

        const uint32_t Ks = sbase + AK_OFF + (t & 1) * AK_SZ;
        const uint32_t Vs = sbase + AV_OFF + (t & 1) * AV_SZ;
        const uint32_t Qs = sbase + AQ_OFF;
        const uint32_t Pw = sbase + AP_OFF + wid * AP_SZ;

        float sacc[8][4];
        #pragma unroll
        for (int nf = 0; nf < 8; nf++)
            #pragma unroll
            for (int r = 0; r < 4; r++) sacc[nf][r] = 0.f;

        #pragma unroll
        for (int ks = 0; ks < 4; ks++) {
            uint32_t af[4];
            ldmx4(af, Qs + (uint32_t)((16 * wid + a_lrow) * 128
                                      + (((2 * ks + a_colhi) ^ a_xor) * 16)));
            #pragma unroll
            for (int nf = 0; nf < 8; nf++) {
                uint32_t bf[2];
                ldmx2(bf, Ks + (uint32_t)((nf * 8 + b_lrow) * 128
                                          + (((2 * ks + b_chi) ^ (b_lrow & 7)) * 16)));
                mma_f16(sacc[nf], af, bf);
            }
        }

        const bool diag = (t == ntiles - 1);
        float mx0 = -1e30f, mx1 = -1e30f;
        #pragma unroll
        for (int nf = 0; nf < 8; nf++) {
            if (diag) {
                const int j = t * 64 + 8 * nf + 2 * t4;
                if (j     > qr0)     sacc[nf][0] = -1e30f;
                if (j + 1 > qr0)     sacc[nf][1] = -1e30f;
                if (j     > qr0 + 8) sacc[nf][2] = -1e30f;
                if (j + 1 > qr0 + 8) sacc[nf][3] = -1e30f;
            }
            mx0 = fmaxf(mx0, fmaxf(sacc[nf][0], sacc[nf][1]));
            mx1 = fmaxf(mx1, fmaxf(sacc[nf][2], sacc[nf][3]));
        }
        mx0 = fmaxf(mx0, __shfl_xor_sync(0xffffffffu, mx0, 1));
        mx0 = fmaxf(mx0, __shfl_xor_sync(0xffffffffu, mx0, 2));
        mx1 = fmaxf(mx1, __shfl_xor_sync(0xffffffffu, mx1, 1));
        mx1 = fmaxf(mx1, __shfl_xor_sync(0xffffffffu, mx1, 2));

        const float mn0 = fmaxf(m0, mx0);
        const float mn1 = fmaxf(m1, mx1);
        const float c0 = __expf(m0 - mn0);
        const float c1 = __expf(m1 - mn1);
        float sum0 = 0.f, sum1 = 0.f;
        #pragma unroll
        for (int nf = 0; nf < 8; nf++) {
            sacc[nf][0] = __expf(sacc[nf][0] - mn0);
            sacc[nf][1] = __expf(sacc[nf][1] - mn0);
            sacc[nf][2] = __expf(sacc[nf][2] - mn1);
            sacc[nf][3] = __expf(sacc[nf][3] - mn1);
            sum0 += sacc[nf][0] + sacc[nf][1];
            sum1 += sacc[nf][2] + sacc[nf][3];
        }
        sum0 += __shfl_xor_sync(0xffffffffu, sum0, 1);
        sum0 += __shfl_xor_sync(0xffffffffu, sum0, 2);
        sum1 += __shfl_xor_sync(0xffffffffu, sum1, 1);
        sum1 += __shfl_xor_sync(0xffffffffu, sum1, 2);
        l0 = l0 * c0 + sum0;
        l1 = l1 * c1 + sum1;
        m0 = mn0; m1 = mn1;

        #pragma unroll
        for (int nf = 0; nf < 8; nf++) {
            oacc[nf][0] *= c0; oacc[nf][1] *= c0;
            oacc[nf][2] *= c1; oacc[nf][3] *= c1;
            const uint32_t p0 = Pw + (uint32_t)(g * 128 + ((nf ^ (g & 7)) * 16) + t4 * 4);
            const uint32_t p1 = Pw + (uint32_t)((g + 8) * 128 + ((nf ^ ((g + 8) & 7)) * 16) + t4 * 4);
            *(__half2*)(smc + (p0 - sbase)) = __floats2half2_rn(sacc[nf][0], sacc[nf][1]);
            *(__half2*)(smc + (p1 - sbase)) = __floats2half2_rn(sacc[nf][2], sacc[nf][3]);
        }
        __syncwarp();

        #pragma unroll
        for (int ks = 0; ks < 4; ks++) {
            uint32_t af[4];
            ldmx4(af, Pw + (uint32_t)(a_lrow * 128
                                      + (((2 * ks + a_colhi) ^ a_xor) * 16)));
            const int vrow = 16 * ks + vl;
            #pragma unroll
            for (int nf = 0; nf < 8; nf++) {
                uint32_t bf[2];
                ldmx2t(bf, Vs + (uint32_t)(vrow * 128 + ((nf ^ (vrow & 7)) * 16)));
                mma_f16(oacc[nf], af, bf);
            }
        }
    }

    const float inv0 = 1.0f / l0;
    const float inv1 = 1.0f / l1;
    const int h = hb & (NHEAD - 1);
    const int b = hb >> 4;
    const size_t row0 = (size_t)b * SEQ + q0 + 16 * wid + g;
    #pragma unroll
    for (int nf = 0; nf < 8; nf++) {
        const int col = h * 64 + 8 * nf + 2 * t4;
        *(__half2*)&out[row0 * HDIM + col] =
            __floats2half2_rn(oacc[nf][0] * inv0, oacc[nf][1] * inv0);
        *(__half2*)&out[(row0 + 8) * HDIM + col] =
            __floats2half2_rn(oacc[nf][2] * inv1, oacc[nf][3] * inv1);
    }
}

// ---------------------------------------------------------------------------
// LayerNorm: one warp per row, one-pass moments.
// ---------------------------------------------------------------------------
template <int HALF_OUT>
__global__ void __launch_bounds__(256)
ln_kernel(const float* __restrict__ x, const float* __restrict__ gamma,
          const float* __restrict__ beta, void* __restrict__ yv) {
    const int warp = threadIdx.x >> 5;
    const int lane = threadIdx.x & 31;
    const int row = blockIdx.x * 8 + warp;
    const float* xr = x + (size_t)row * HDIM;

    float4 v[8];
    float s = 0.f, s2 = 0.f;
    #pragma unroll
    for (int j = 0; j < 8; j++) {
        v[j] = *(const float4*)(xr + lane * 4 + j * 128);
        s  += v[j].x + v[j].y + v[j].z + v[j].w;
        s2 += v[j].x * v[j].x + v[j].y * v[j].y
            + v[j].z * v[j].z + v[j].w * v[j].w;
    }
    #pragma unroll
    for (int off = 16; off; off >>= 1) {
        s  += __shfl_xor_sync(0xffffffffu, s,  off);
        s2 += __shfl_xor_sync(0xffffffffu, s2, off);
    }
    const float mean = s * (1.0f / HDIM);
    const float var  = s2 * (1.0f / HDIM) - mean * mean;
    const float rs   = rsqrtf(var + 1e-5f);

    #pragma unroll
    for (int j = 0; j < 8; j++) {
        const int ci = lane * 4 + j * 128;
        const float4 gv = *(const float4*)(gamma + ci);
        const float4 bv = *(const float4*)(beta + ci);
        const float o0 = (v[j].x - mean) * rs * gv.x + bv.x;
        const float o1 = (v[j].y - mean) * rs * gv.y + bv.y;
        const float o2 = (v[j].z - mean) * rs * gv.z + bv.z;
        const float o3 = (v[j].w - mean) * rs * gv.w + bv.w;
        if (HALF_OUT) {
            __half2 h01 = __floats2half2_rn(o0, o1);
            __half2 h23 = __floats2half2_rn(o2, o3);
            uint2 pk;
            pk.x = *(uint32_t*)&h01;
            pk.y = *(uint32_t*)&h23;
            *(uint2*)((__half*)yv + (size_t)row * HDIM + ci) = pk;
        } else {
            *(float4*)((float*)yv + (size_t)row * HDIM + ci) =
                make_float4(o0, o1, o2, o3);
        }
    }
}

// ---------------------------------------------------------------------------
// Launch
// ---------------------------------------------------------------------------
extern "C" void kernel_launch(void* const* d_in, const int* in_sizes, int n_in,
                              void* d_out, int out_size) {
    const float* embeds = (const float*)d_in[0];
    const float* Wqkv  = (const float*)d_in[2];
    const float* bqkv  = (const float*)d_in[3];
    const float* Wo    = (const float*)d_in[4];
    const float* bo    = (const float*)d_in[5];
    const float* ln1g  = (const float*)d_in[6];
    const float* ln1b  = (const float*)d_in[7];
    const float* ln2g  = (const float*)d_in[8];
    const float* ln2b  = (const float*)d_in[9];
    const float* Wfc   = (const float*)d_in[10];
    const float* bfc   = (const float*)d_in[11];
    const float* Wproj = (const float*)d_in[12];
    const float* bproj = (const float*)d_in[13];
    const float* lnfg  = (const float*)d_in[14];
    const float* lnfb  = (const float*)d_in[15];

    float *h;
    __half *xh, *attnh, *fch, *qh, *kh, *vh, *Wqkvh, *Woh, *Wfch, *Wprojh;
    cudaGetSymbolAddress((void**)&h,      g_h);
    cudaGetSymbolAddress((void**)&xh,     g_xh);
    cudaGetSymbolAddress((void**)&attnh,  g_attnh);
    cudaGetSymbolAddress((void**)&fch,    g_fch);
    cudaGetSymbolAddress((void**)&qh,     g_qheads);
    cudaGetSymbolAddress((void**)&kh,     g_kheads);
    cudaGetSymbolAddress((void**)&vh,     g_vheads);
    cudaGetSymbolAddress((void**)&Wqkvh,  g_Wqkvh);
    cudaGetSymbolAddress((void**)&Woh,    g_Woh);
    cudaGetSymbolAddress((void**)&Wfch,   g_Wfch);
    cudaGetSymbolAddress((void**)&Wprojh, g_Wprojh);

    cudaFuncSetAttribute(mma_gemm<0>, cudaFuncAttributeMaxDynamicSharedMemorySize, GEMM_SMEM);
    cudaFuncSetAttribute(mma_gemm<1>, cudaFuncAttributeMaxDynamicSharedMemorySize, GEMM_SMEM);
    cudaFuncSetAttribute(mma_gemm<2>, cudaFuncAttributeMaxDynamicSharedMemorySize, GEMM_SMEM);
    cudaFuncSetAttribute(mma_gemm_qkv, cudaFuncAttributeMaxDynamicSharedMemorySize, GEMM_SMEM);
    cudaFuncSetAttribute(mma_attn,     cudaFuncAttributeMaxDynamicSharedMemorySize, ATTN_SMEM);

    convert_w<<<dim3(3 * HDIM / 64, HDIM / 64, NLAYER), dim3(32, 8)>>>(Wqkv, Wqkvh, HDIM, 3 * HDIM);
    convert_w<<<dim3(HDIM / 64, HDIM / 64, NLAYER), dim3(32, 8)>>>(Wo, Woh, HDIM, HDIM);
    convert_w<<<dim3(FFDIM / 64, HDIM / 64, NLAYER), dim3(32, 8)>>>(Wfc, Wfch, HDIM, FFDIM);
    convert_w<<<dim3(HDIM / 64, FFDIM / 64, NLAYER), dim3(32, 8)>>>(Wproj, Wprojh, FFDIM, HDIM);

    for (int l = 0; l < NLAYER; l++) {
        const float* hin = (l == 0) ? embeds : h;
        ln_kernel<1><<<MTOK / 8, 256>>>(hin, ln1g + l * HDIM, ln1b + l * HDIM, xh);
        mma_gemm_qkv<<<dim3(3 * HDIM / 128, MTOK / 128), 256, GEMM_SMEM>>>(
            xh, Wqkvh + (size_t)l * HDIM * 3 * HDIM, bqkv + (size_t)l * 3 * HDIM,
            qh, kh, vh, HDIM);
        mma_attn<<<dim3(SEQ / 64, BATCH * NHEAD), 128, ATTN_SMEM>>>(qh, kh, vh, attnh);
        mma_gemm<1><<<dim3(HDIM / 128, MTOK / 128), 256, GEMM_SMEM>>>(
            attnh, Woh + (size_t)l * HDIM * HDIM, bo + (size_t)l * HDIM,
            hin, h, MTOK, HDIM, HDIM);
        ln_kernel<1><<<MTOK / 8, 256>>>(h, ln2g + l * HDIM, ln2b + l * HDIM, xh);
        mma_gemm<2><<<dim3(FFDIM / 128, MTOK / 128), 256, GEMM_SMEM>>>(
            xh, Wfch + (size_t)l * HDIM * FFDIM, bfc + (size_t)l * FFDIM,
            nullptr, fch, MTOK, FFDIM, HDIM);
        mma_gemm<1><<<dim3(HDIM / 128, MTOK / 128), 256, GEMM_SMEM>>>(
            fch, Wprojh + (size_t)l * FFDIM * HDIM, bproj + (size_t)l * HDIM,
            h, h, MTOK, HDIM, FFDIM);
    }
    ln_kernel<0><<<MTOK / 8, 256>>>(h, lnfg, lnfb, d_out);
}

// round 15
// speedup vs baseline: 1.0801x; 1.0056x over previous
#include <cuda_runtime.h>
#include <cuda_fp16.h>
#include <math.h>
#include <stdint.h>

// Problem constants
#define NLAYER 4
#define HDIM   1024
#define NHEAD  16
#define HEADD  64
#define FFDIM  4096
#define BATCH  4
#define SEQ    1024
#define MTOK   (BATCH * SEQ)   // 4096 tokens

// ---------------------------------------------------------------------------
// Scratch (allocation-free: __device__ globals)
// ---------------------------------------------------------------------------
__device__ float g_h   [MTOK * HDIM];
__device__ __align__(16) __half g_xh   [MTOK * HDIM];
__device__ __align__(16) __half g_attnh[MTOK * HDIM];
__device__ __align__(16) __half g_fch  [MTOK * FFDIM];
// Per-head Q/K/V, layout [b*NH][S][64] half
__device__ __align__(16) __half g_qheads[MTOK * HDIM];
__device__ __align__(16) __half g_kheads[MTOK * HDIM];
__device__ __align__(16) __half g_vheads[MTOK * HDIM];
// Converted weights, layout [l][N][K] half
__device__ __align__(16) __half g_Wqkvh [NLAYER * 3 * HDIM * HDIM];
__device__ __align__(16) __half g_Woh   [NLAYER * HDIM * HDIM];
__device__ __align__(16) __half g_Wfch  [NLAYER * HDIM * FFDIM];
__device__ __align__(16) __half g_Wprojh[NLAYER * FFDIM * HDIM];

// ---------------------------------------------------------------------------
// PTX helpers
// ---------------------------------------------------------------------------
__device__ __forceinline__ uint32_t smem_u32(const void* p) {
    uint32_t a;
    asm("{ .reg .u64 t; cvta.to.shared.u64 t, %1; cvt.u32.u64 %0, t; }" : "=r"(a) : "l"(p));
    return a;
}
__device__ __forceinline__ void cp_async16(uint32_t s, const void* g) {
    asm volatile("cp.async.cg.shared.global [%0], [%1], 16;\n" :: "r"(s), "l"(g));
}
__device__ __forceinline__ void cp_commit() {
    asm volatile("cp.async.commit_group;\n" ::: "memory");
}
__device__ __forceinline__ void mma_f16(float* c, const uint32_t* a, const uint32_t* b) {
    asm volatile(
        "mma.sync.aligned.m16n8k16.row.col.f32.f16.f16.f32 "
        "{%0,%1,%2,%3}, {%4,%5,%6,%7}, {%8,%9}, {%0,%1,%2,%3};"
        : "+f"(c[0]), "+f"(c[1]), "+f"(c[2]), "+f"(c[3])
        : "r"(a[0]), "r"(a[1]), "r"(a[2]), "r"(a[3]), "r"(b[0]), "r"(b[1]));
}
__device__ __forceinline__ void ldmx4(uint32_t* r, uint32_t addr) {
    asm volatile("ldmatrix.sync.aligned.m8n8.x4.shared.b16 {%0,%1,%2,%3}, [%4];"
        : "=r"(r[0]), "=r"(r[1]), "=r"(r[2]), "=r"(r[3]) : "r"(addr));
}
__device__ __forceinline__ void ldmx2(uint32_t* r, uint32_t addr) {
    asm volatile("ldmatrix.sync.aligned.m8n8.x2.shared.b16 {%0,%1}, [%2];"
        : "=r"(r[0]), "=r"(r[1]) : "r"(addr));
}
__device__ __forceinline__ void ldmx2t(uint32_t* r, uint32_t addr) {
    asm volatile("ldmatrix.sync.aligned.m8n8.x2.trans.shared.b16 {%0,%1}, [%2];"
        : "=r"(r[0]), "=r"(r[1]) : "r"(addr));
}

// ---------------------------------------------------------------------------
// fp16 mma GEMM config (R6/R12 proven — FROZEN):
// CTA 128x128, 8 warps (warp tile 64x32), BK=64, 3-stage cp.async.
// ---------------------------------------------------------------------------
#define STAGES    3
#define AT_BYTES  16384
#define STAGE_SZ  32768
#define GEMM_SMEM (STAGES * STAGE_SZ)

#define GEMM_MAINLOOP(A, Bt, K)                                                  \
    const uint32_t sbase = smem_u32(smem);                                       \
    const int tid  = threadIdx.x;                                                \
    const int wid  = tid >> 5;                                                   \
    const int lane = tid & 31;                                                   \
    const int g    = lane >> 2;                                                  \
    const int t4   = lane & 3;                                                   \
    const int M0 = blockIdx.y * 128;                                             \
    const int N0 = blockIdx.x * 128;                                             \
    const int wm0 = (wid >> 2) * 64;                                             \
    const int wn0 = (wid & 3) * 32;                                              \
    const int iters = (K) >> 6;                                                  \
    const int a_lrow  = (lane & 7) + 8 * ((lane >> 3) & 1);                      \
    const int a_colhi = lane >> 4;                                               \
    const int a_xor   = a_lrow & 7;                                              \
    const int b_lrow  = lane & 7;                                                \
    const int b_chi   = (lane >> 3) & 1;                                         \
    auto load_stage = [&](int s, int k0) {                                       \
        const uint32_t sA = sbase + s * STAGE_SZ;                                \
        const uint32_t sB = sA + AT_BYTES;                                       \
        _Pragma("unroll")                                                        \
        for (int i = 0; i < 4; i++) {                                            \
            const int c = tid + 256 * i;                                         \
            const int r = c >> 3, cc = c & 7;                                    \
            cp_async16(sA + (uint32_t)(r * 128 + ((cc ^ (r & 7)) * 16)),         \
                       (A) + (size_t)(M0 + r) * (K) + k0 + cc * 8);              \
        }                                                                        \
        _Pragma("unroll")                                                        \
        for (int i = 0; i < 4; i++) {                                            \
            const int c = tid + 256 * i;                                         \
            const int r = c >> 3, cc = c & 7;                                    \
            cp_async16(sB + (uint32_t)(r * 128 + ((cc ^ (r & 7)) * 16)),         \
                       (Bt) + (size_t)(N0 + r) * (K) + k0 + cc * 8);             \
        }                                                                        \
        cp_commit();                                                             \
    };                                                                           \
    float acc[4][4][4];                                                          \
    _Pragma("unroll")                                                            \
    for (int mf = 0; mf < 4; mf++)                                               \
        _Pragma("unroll")                                                        \
        for (int nf = 0; nf < 4; nf++)                                           \
            _Pragma("unroll")                                                    \
            for (int r = 0; r < 4; r++) acc[mf][nf][r] = 0.f;                    \
    load_stage(0, 0);                                                            \
    load_stage(1, 64);                                                           \
    for (int it = 0; it < iters; it++) {                                         \
        asm volatile("cp.async.wait_group 1;\n" ::: "memory");                   \
        __syncthreads();                                                         \
        if (it + 2 < iters) load_stage((it + 2) % STAGES, (it + 2) * 64);        \
        else                cp_commit();                                         \
        const uint32_t sA = sbase + (it % STAGES) * STAGE_SZ;                    \
        const uint32_t sB = sA + AT_BYTES;                                       \
        _Pragma("unroll")                                                        \
        for (int ks = 0; ks < 4; ks++) {                                         \
            uint32_t af[4][4], bf[4][2];                                         \
            _Pragma("unroll")                                                    \
            for (int mf = 0; mf < 4; mf++) {                                     \
                const uint32_t adr = sA                                          \
                    + (uint32_t)((wm0 + mf * 16 + a_lrow) * 128                  \
                                 + (((2 * ks + a_colhi) ^ a_xor) * 16));         \
                ldmx4(af[mf], adr);                                              \
            }                                                                    \
            _Pragma("unroll")                                                    \
            for (int nf = 0; nf < 4; nf++) {                                     \
                const uint32_t badr = sB                                         \
                    + (uint32_t)((wn0 + nf * 8 + b_lrow) * 128                   \
                                 + (((2 * ks + b_chi) ^ (b_lrow & 7)) * 16));    \
                ldmx2(bf[nf], badr);                                             \
            }                                                                    \
            _Pragma("unroll")                                                    \
            for (int mf = 0; mf < 4; mf++)                                       \
                _Pragma("unroll")                                                \
                for (int nf = 0; nf < 4; nf++)                                   \
                    mma_f16(acc[mf][nf], af[mf], bf[nf]);                        \
        }                                                                        \
    }

// Generic epilogue GEMM. EPI: 0=bias->f32, 1=bias+res->f32, 2=bias+gelu->half
template <int EPI>
__global__ void __launch_bounds__(256, 2)
mma_gemm(const __half* __restrict__ A, const __half* __restrict__ Bt,
         const float* __restrict__ bias, const float* __restrict__ Res,
         void* __restrict__ Cout, int M, int N, int K) {
    extern __shared__ char smem[];
    GEMM_MAINLOOP(A, Bt, K)

    #pragma unroll
    for (int mf = 0; mf < 4; mf++) {
        #pragma unroll
        for (int nf = 0; nf < 4; nf++) {
            const int col  = N0 + wn0 + nf * 8 + t4 * 2;
            const int row0 = M0 + wm0 + mf * 16 + g;
            const float b0 = bias[col], b1 = bias[col + 1];
            #pragma unroll
            for (int half_i = 0; half_i < 2; half_i++) {
                const int row = row0 + half_i * 8;
                float v0 = acc[mf][nf][half_i * 2 + 0] + b0;
                float v1 = acc[mf][nf][half_i * 2 + 1] + b1;
                if (EPI == 1) {
                    const float2 rv = *(const float2*)(Res + (size_t)row * N + col);
                    v0 += rv.x; v1 += rv.y;
                }
                if (EPI == 2) {
                    float u0 = 0.7978845608028654f * (v0 + 0.044715f * v0 * v0 * v0);
                    float u1 = 0.7978845608028654f * (v1 + 0.044715f * v1 * v1 * v1);
                    v0 = 0.5f * v0 * (1.0f + tanhf(u0));
                    v1 = 0.5f * v1 * (1.0f + tanhf(u1));
                    *(__half2*)((__half*)Cout + (size_t)row * N + col) =
                        __floats2half2_rn(v0, v1);
                } else {
                    *(float2*)((float*)Cout + (size_t)row * N + col) =
                        make_float2(v0, v1);
                }
            }
        }
    }
}

// QKV GEMM with fused RoPE epilogue -> per-head half Q/K/V buffers.
__global__ void __launch_bounds__(256, 2)
mma_gemm_qkv(const __half* __restrict__ A, const __half* __restrict__ Bt,
             const float* __restrict__ bias,
             __half* __restrict__ Qh, __half* __restrict__ Kh,
             __half* __restrict__ Vh, int K) {
    extern __shared__ char smem[];
    GEMM_MAINLOOP(A, Bt, K)

    #pragma unroll
    for (int nf = 0; nf < 4; nf++) {
        const int col = N0 + wn0 + nf * 8 + t4 * 2;     // even column
        const int sec = col >> 10;                       // 0=q 1=k 2=v
        const int d   = col & 1023;
        const int hh  = d >> 6;
        const int dd  = d & 63;
        const int ip  = dd >> 1;                         // rope pair index
        const float invfreq = exp2f((float)ip * -0.41524101186092029f);
        const float b0 = bias[col], b1 = bias[col + 1];
        #pragma unroll
        for (int mf = 0; mf < 4; mf++) {
            #pragma unroll
            for (int half_i = 0; half_i < 2; half_i++) {
                const int row = M0 + wm0 + mf * 16 + g + half_i * 8;
                const int pos = row & (SEQ - 1);
                const int bb  = row >> 10;
                const size_t o = ((size_t)(bb * NHEAD + hh) * SEQ + pos) * 64 + dd;
                float v0 = acc[mf][nf][half_i * 2 + 0] + b0;
                float v1 = acc[mf][nf][half_i * 2 + 1] + b1;
                if (sec == 2) {
                    *(__half2*)&Vh[o] = __floats2half2_rn(v0, v1);
                } else {
                    float sn, cs;
                    sincosf((float)pos * invfreq, &sn, &cs);
                    const float r0 = v0 * cs - v1 * sn;
                    const float r1 = v1 * cs + v0 * sn;
                    if (sec == 0)
                        *(__half2*)&Qh[o] = __floats2half2_rn(r0 * 0.125f, r1 * 0.125f);
                    else
                        *(__half2*)&Kh[o] = __floats2half2_rn(r0, r1);
                }
            }
        }
    }
}

// ---------------------------------------------------------------------------
// Weight convert + transpose (R12 verified): W[l][K][N] fp32 -> Wh[l][N][K] half.
// Tile 64(k) x 32(n). Coalesced fp32 reads; contiguous half2 writes.
// ---------------------------------------------------------------------------
__global__ void convert_w(const float* __restrict__ W, __half* __restrict__ Wh,
                          int K, int N) {
    __shared__ float t[64][33];
    const int l = blockIdx.z;
    const float* Wl = W + (size_t)l * K * N;
    __half* Wo = Wh + (size_t)l * K * N;
    const int n0 = blockIdx.x * 32, k0 = blockIdx.y * 64;
    const int tx = threadIdx.x, ty = threadIdx.y;   // (32, 8)
    #pragma unroll
    for (int i = 0; i < 64; i += 8)
        t[ty + i][tx] = Wl[(size_t)(k0 + ty + i) * N + n0 + tx];
    __syncthreads();
    #pragma unroll
    for (int i = 0; i < 32; i += 8) {
        const int n = i + ty;
        const __half2 hv = __floats2half2_rn(t[2 * tx][n], t[2 * tx + 1][n]);
        *(__half2*)&Wo[(size_t)(n0 + n) * K + k0 + 2 * tx] = hv;
    }
}

// ---------------------------------------------------------------------------
// fp16 tensor-core flash attention (causal), heavy-first CTA order (R12).
// CTA = (qtile 64 rows, head*batch), 128 threads (4 warps x 16 q rows).
// ---------------------------------------------------------------------------
#define AQ_OFF 0
#define AK_OFF 8192
#define AK_SZ  8192
#define AV_OFF 24576
#define AV_SZ  8192
#define AP_OFF 40960
#define AP_SZ  2048
#define ATTN_SMEM 49152

__global__ void __launch_bounds__(128)
mma_attn(const __half* __restrict__ Qh, const __half* __restrict__ Kh,
         const __half* __restrict__ Vh, __half* __restrict__ out) {
    extern __shared__ char smc[];
    const uint32_t sbase = smem_u32(smc);
    const int tid = threadIdx.x;
    const int wid = tid >> 5;
    const int lane = tid & 31;
    const int g = lane >> 2;
    const int t4 = lane & 3;

    const int qt = gridDim.x - 1 - blockIdx.x;   // heavy-first
    const int hb = blockIdx.y;
    const int q0 = qt * 64;
    const int ntiles = qt + 1;
    const size_t headbase = (size_t)hb * SEQ * 64;

    const int a_lrow  = (lane & 7) + 8 * ((lane >> 3) & 1);
    const int a_colhi = lane >> 4;
    const int a_xor   = a_lrow & 7;
    const int b_lrow  = lane & 7;
    const int b_chi   = (lane >> 3) & 1;
    const int vl      = lane & 15;

    auto load_tile = [&](uint32_t dst, const __half* src) {
        #pragma unroll
        for (int i = 0; i < 4; i++) {
            const int c = tid + 128 * i;
            const int r = c >> 3, ch = c & 7;
            cp_async16(dst + (uint32_t)(r * 128 + ((ch ^ (r & 7)) * 16)),
                       src + r * 64 + ch * 8);
        }
    };

    load_tile(sbase + AQ_OFF, Qh + headbase + (size_t)q0 * 64);
    load_tile(sbase + AK_OFF, Kh + headbase);
    load_tile(sbase + AV_OFF, Vh + headbase);
    cp_commit();

    float oacc[8][4];
    #pragma unroll
    for (int nf = 0; nf < 8; nf++)
        #pragma unroll
        for (int r = 0; r < 4; r++) oacc[nf][r] = 0.f;
    float m0 = -1e30f, m1 = -1e30f, l0 = 0.f, l1 = 0.f;

    const int qr0 = q0 + 16 * wid + g;

    for (int t = 0; t < ntiles; t++) {
        asm volatile("cp.async.wait_group 0;\n" ::: "memory");
        __syncthreads();

        if (t + 1 < ntiles) {
            const size_t kvoff = headbase + (size_t)(t + 1) * 64 * 64;
            load_tile(sbase + AK_OFF + ((t + 1) & 1) * AK_SZ, Kh + kvoff);
            load_tile(sbase + AV_OFF + ((t + 1) & 1) * AV_SZ, Vh + kvoff);
            cp_commit();
        }

        const uint32_t Ks = sbase + AK_OFF + (t & 1) * AK_SZ;
        const uint32_t Vs = sbase + AV_OFF + (t & 1) * AV_SZ;
        const uint32_t Qs = sbase + AQ_OFF;
        const uint32_t Pw = sbase + AP_OFF + wid * AP_SZ;

        float sacc[8][4];
        #pragma unroll
        for (int nf = 0; nf < 8; nf++)
            #pragma unroll
            for (int r = 0; r < 4; r++) sacc[nf][r] = 0.f;

        #pragma unroll
        for (int ks = 0; ks < 4; ks++) {
            uint32_t af[4];
            ldmx4(af, Qs + (uint32_t)((16 * wid + a_lrow) * 128
                                      + (((2 * ks + a_colhi) ^ a_xor) * 16)));
            #pragma unroll
            for (int nf = 0; nf < 8; nf++) {
                uint32_t bf[2];
                ldmx2(bf, Ks + (uint32_t)((nf * 8 + b_lrow) * 128
                                          + (((2 * ks + b_chi) ^ (b_lrow & 7)) * 16)));
                mma_f16(sacc[nf], af, bf);
            }
        }

        const bool diag = (t == ntiles - 1);
        float mx0 = -1e30f, mx1 = -1e30f;
        #pragma unroll
        for (int nf = 0; nf < 8; nf++) {
            if (diag) {
                const int j = t * 64 + 8 * nf + 2 * t4;
                if (j     > qr0)     sacc[nf][0] = -1e30f;
                if (j + 1 > qr0)     sacc[nf][1] = -1e30f;
                if (j     > qr0 + 8) sacc[nf][2] = -1e30f;
                if (j + 1 > qr0 + 8) sacc[nf][3] = -1e30f;
            }
            mx0 = fmaxf(mx0, fmaxf(sacc[nf][0], sacc[nf][1]));
            mx1 = fmaxf(mx1, fmaxf(sacc[nf][2], sacc[nf][3]));
        }
        mx0 = fmaxf(mx0, __shfl_xor_sync(0xffffffffu, mx0, 1));
        mx0 = fmaxf(mx0, __shfl_xor_sync(0xffffffffu, mx0, 2));
        mx1 = fmaxf(mx1, __shfl_xor_sync(0xffffffffu, mx1, 1));
        mx1 = fmaxf(mx1, __shfl_xor_sync(0xffffffffu, mx1, 2));

        const float mn0 = fmaxf(m0, mx0);
        const float mn1 = fmaxf(m1, mx1);
        const float c0 = __expf(m0 - mn0);
        const float c1 = __expf(m1 - mn1);
        float sum0 = 0.f, sum1 = 0.f;
        #pragma unroll
        for (int nf = 0; nf < 8; nf++) {
            sacc[nf][0] = __expf(sacc[nf][0] - mn0);
            sacc[nf][1] = __expf(sacc[nf][1] - mn0);
            sacc[nf][2] = __expf(sacc[nf][2] - mn1);
            sacc[nf][3] = __expf(sacc[nf][3] - mn1);
            sum0 += sacc[nf][0] + sacc[nf][1];
            sum1 += sacc[nf][2] + sacc[nf][3];
        }
        sum0 += __shfl_xor_sync(0xffffffffu, sum0, 1);
        sum0 += __shfl_xor_sync(0xffffffffu, sum0, 2);
        sum1 += __shfl_xor_sync(0xffffffffu, sum1, 1);
        sum1 += __shfl_xor_sync(0xffffffffu, sum1, 2);
        l0 = l0 * c0 + sum0;
        l1 = l1 * c1 + sum1;
        m0 = mn0; m1 = mn1;

        #pragma unroll
        for (int nf = 0; nf < 8; nf++) {
            oacc[nf][0] *= c0; oacc[nf][1] *= c0;
            oacc[nf][2] *= c1; oacc[nf][3] *= c1;
            const uint32_t p0 = Pw + (uint32_t)(g * 128 + ((nf ^ (g & 7)) * 16) + t4 * 4);
            const uint32_t p1 = Pw + (uint32_t)((g + 8) * 128 + ((nf ^ ((g + 8) & 7)) * 16) + t4 * 4);
            *(__half2*)(smc + (p0 - sbase)) = __floats2half2_rn(sacc[nf][0], sacc[nf][1]);
            *(__half2*)(smc + (p1 - sbase)) = __floats2half2_rn(sacc[nf][2], sacc[nf][3]);
        }
        __syncwarp();

        #pragma unroll
        for (int ks = 0; ks < 4; ks++) {
            uint32_t af[4];
            ldmx4(af, Pw + (uint32_t)(a_lrow * 128
                                      + (((2 * ks + a_colhi) ^ a_xor) * 16)));
            const int vrow = 16 * ks + vl;
            #pragma unroll
            for (int nf = 0; nf < 8; nf++) {
                uint32_t bf[2];
                ldmx2t(bf, Vs + (uint32_t)(vrow * 128 + ((nf ^ (vrow & 7)) * 16)));
                mma_f16(oacc[nf], af, bf);
            }
        }
    }

    const float inv0 = 1.0f / l0;
    const float inv1 = 1.0f / l1;
    const int h = hb & (NHEAD - 1);
    const int b = hb >> 4;
    const size_t row0 = (size_t)b * SEQ + q0 + 16 * wid + g;
    #pragma unroll
    for (int nf = 0; nf < 8; nf++) {
        const int col = h * 64 + 8 * nf + 2 * t4;
        *(__half2*)&out[row0 * HDIM + col] =
            __floats2half2_rn(oacc[nf][0] * inv0, oacc[nf][1] * inv0);
        *(__half2*)&out[(row0 + 8) * HDIM + col] =
            __floats2half2_rn(oacc[nf][2] * inv1, oacc[nf][3] * inv1);
    }
}

// ---------------------------------------------------------------------------
// LayerNorm: one warp per row, one-pass moments.
// ---------------------------------------------------------------------------
template <int HALF_OUT>
__global__ void __launch_bounds__(256)
ln_kernel(const float* __restrict__ x, const float* __restrict__ gamma,
          const float* __restrict__ beta, void* __restrict__ yv) {
    const int warp = threadIdx.x >> 5;
    const int lane = threadIdx.x & 31;
    const int row = blockIdx.x * 8 + warp;
    const float* xr = x + (size_t)row * HDIM;

    float4 v[8];
    float s = 0.f, s2 = 0.f;
    #pragma unroll
    for (int j = 0; j < 8; j++) {
        v[j] = *(const float4*)(xr + lane * 4 + j * 128);
        s  += v[j].x + v[j].y + v[j].z + v[j].w;
        s2 += v[j].x * v[j].x + v[j].y * v[j].y
            + v[j].z * v[j].z + v[j].w * v[j].w;
    }
    #pragma unroll
    for (int off = 16; off; off >>= 1) {
        s  += __shfl_xor_sync(0xffffffffu, s,  off);
        s2 += __shfl_xor_sync(0xffffffffu, s2, off);
    }
    const float mean = s * (1.0f / HDIM);
    const float var  = s2 * (1.0f / HDIM) - mean * mean;
    const float rs   = rsqrtf(var + 1e-5f);

    #pragma unroll
    for (int j = 0; j < 8; j++) {
        const int ci = lane * 4 + j * 128;
        const float4 gv = *(const float4*)(gamma + ci);
        const float4 bv = *(const float4*)(beta + ci);
        const float o0 = (v[j].x - mean) * rs * gv.x + bv.x;
        const float o1 = (v[j].y - mean) * rs * gv.y + bv.y;
        const float o2 = (v[j].z - mean) * rs * gv.z + bv.z;
        const float o3 = (v[j].w - mean) * rs * gv.w + bv.w;
        if (HALF_OUT) {
            __half2 h01 = __floats2half2_rn(o0, o1);
            __half2 h23 = __floats2half2_rn(o2, o3);
            uint2 pk;
            pk.x = *(uint32_t*)&h01;
            pk.y = *(uint32_t*)&h23;
            *(uint2*)((__half*)yv + (size_t)row * HDIM + ci) = pk;
        } else {
            *(float4*)((float*)yv + (size_t)row * HDIM + ci) =
                make_float4(o0, o1, o2, o3);
        }
    }
}

// ---------------------------------------------------------------------------
// Launch
// ---------------------------------------------------------------------------
extern "C" void kernel_launch(void* const* d_in, const int* in_sizes, int n_in,
                              void* d_out, int out_size) {
    const float* embeds = (const float*)d_in[0];
    const float* Wqkv  = (const float*)d_in[2];
    const float* bqkv  = (const float*)d_in[3];
    const float* Wo    = (const float*)d_in[4];
    const float* bo    = (const float*)d_in[5];
    const float* ln1g  = (const float*)d_in[6];
    const float* ln1b  = (const float*)d_in[7];
    const float* ln2g  = (const float*)d_in[8];
    const float* ln2b  = (const float*)d_in[9];
    const float* Wfc   = (const float*)d_in[10];
    const float* bfc   = (const float*)d_in[11];
    const float* Wproj = (const float*)d_in[12];
    const float* bproj = (const float*)d_in[13];
    const float* lnfg  = (const float*)d_in[14];
    const float* lnfb  = (const float*)d_in[15];

    float *h;
    __half *xh, *attnh, *fch, *qh, *kh, *vh, *Wqkvh, *Woh, *Wfch, *Wprojh;
    cudaGetSymbolAddress((void**)&h,      g_h);
    cudaGetSymbolAddress((void**)&xh,     g_xh);
    cudaGetSymbolAddress((void**)&attnh,  g_attnh);
    cudaGetSymbolAddress((void**)&fch,    g_fch);
    cudaGetSymbolAddress((void**)&qh,     g_qheads);
    cudaGetSymbolAddress((void**)&kh,     g_kheads);
    cudaGetSymbolAddress((void**)&vh,     g_vheads);
    cudaGetSymbolAddress((void**)&Wqkvh,  g_Wqkvh);
    cudaGetSymbolAddress((void**)&Woh,    g_Woh);
    cudaGetSymbolAddress((void**)&Wfch,   g_Wfch);
    cudaGetSymbolAddress((void**)&Wprojh, g_Wprojh);

    cudaFuncSetAttribute(mma_gemm<0>, cudaFuncAttributeMaxDynamicSharedMemorySize, GEMM_SMEM);
    cudaFuncSetAttribute(mma_gemm<1>, cudaFuncAttributeMaxDynamicSharedMemorySize, GEMM_SMEM);
    cudaFuncSetAttribute(mma_gemm<2>, cudaFuncAttributeMaxDynamicSharedMemorySize, GEMM_SMEM);
    cudaFuncSetAttribute(mma_gemm_qkv, cudaFuncAttributeMaxDynamicSharedMemorySize, GEMM_SMEM);
    cudaFuncSetAttribute(mma_attn,     cudaFuncAttributeMaxDynamicSharedMemorySize, ATTN_SMEM);

    convert_w<<<dim3(3 * HDIM / 32, HDIM / 64, NLAYER), dim3(32, 8)>>>(Wqkv, Wqkvh, HDIM, 3 * HDIM);
    convert_w<<<dim3(HDIM / 32, HDIM / 64, NLAYER), dim3(32, 8)>>>(Wo, Woh, HDIM, HDIM);
    convert_w<<<dim3(FFDIM / 32, HDIM / 64, NLAYER), dim3(32, 8)>>>(Wfc, Wfch, HDIM, FFDIM);
    convert_w<<<dim3(HDIM / 32, FFDIM / 64, NLAYER), dim3(32, 8)>>>(Wproj, Wprojh, FFDIM, HDIM);

    for (int l = 0; l < NLAYER; l++) {
        const float* hin = (l == 0) ? embeds : h;
        ln_kernel<1><<<MTOK / 8, 256>>>(hin, ln1g + l * HDIM, ln1b + l * HDIM, xh);
        mma_gemm_qkv<<<dim3(3 * HDIM / 128, MTOK / 128), 256, GEMM_SMEM>>>(
            xh, Wqkvh + (size_t)l * HDIM * 3 * HDIM, bqkv + (size_t)l * 3 * HDIM,
            qh, kh, vh, HDIM);
        mma_attn<<<dim3(SEQ / 64, BATCH * NHEAD), 128, ATTN_SMEM>>>(qh, kh, vh, attnh);
        mma_gemm<1><<<dim3(HDIM / 128, MTOK / 128), 256, GEMM_SMEM>>>(
            attnh, Woh + (size_t)l * HDIM * HDIM, bo + (size_t)l * HDIM,
            hin, h, MTOK, HDIM, HDIM);
        ln_kernel<1><<<MTOK / 8, 256>>>(h, ln2g + l * HDIM, ln2b + l * HDIM, xh);
        mma_gemm<2><<<dim3(FFDIM / 128, MTOK / 128), 256, GEMM_SMEM>>>(
            xh, Wfch + (size_t)l * HDIM * FFDIM, bfc + (size_t)l * FFDIM,
            nullptr, fch, MTOK, FFDIM, HDIM);
        mma_gemm<1><<<dim3(HDIM / 128, MTOK / 128), 256, GEMM_SMEM>>>(
            fch, Wprojh + (size_t)l * FFDIM * HDIM, bproj + (size_t)l * HDIM,
            h, h, MTOK, HDIM, FFDIM);
    }
    ln_kernel<0><<<MTOK / 8, 256>>>(h, lnfg, lnfb, d_out);
}

// round 16
// speedup vs baseline: 1.0807x; 1.0005x over previous
#include <cuda_runtime.h>
#include <cuda_fp16.h>
#include <math.h>
#include <stdint.h>

// Problem constants
#define NLAYER 4
#define HDIM   1024
#define NHEAD  16
#define HEADD  64
#define FFDIM  4096
#define BATCH  4
#define SEQ    1024
#define MTOK   (BATCH * SEQ)   // 4096 tokens

// ---------------------------------------------------------------------------
// Scratch (allocation-free: __device__ globals)
// ---------------------------------------------------------------------------
__device__ float g_h   [MTOK * HDIM];
__device__ __align__(16) __half g_xh   [MTOK * HDIM];
__device__ __align__(16) __half g_attnh[MTOK * HDIM];
__device__ __align__(16) __half g_fch  [MTOK * FFDIM];
// Per-head Q/K/V, layout [b*NH][S][64] half
__device__ __align__(16) __half g_qheads[MTOK * HDIM];
__device__ __align__(16) __half g_kheads[MTOK * HDIM];
__device__ __align__(16) __half g_vheads[MTOK * HDIM];
// Converted weights, layout [l][N][K] half
__device__ __align__(16) __half g_Wqkvh [NLAYER * 3 * HDIM * HDIM];
__device__ __align__(16) __half g_Woh   [NLAYER * HDIM * HDIM];
__device__ __align__(16) __half g_Wfch  [NLAYER * HDIM * FFDIM];
__device__ __align__(16) __half g_Wprojh[NLAYER * FFDIM * HDIM];

// ---------------------------------------------------------------------------
// PTX helpers
// ---------------------------------------------------------------------------
__device__ __forceinline__ uint32_t smem_u32(const void* p) {
    uint32_t a;
    asm("{ .reg .u64 t; cvta.to.shared.u64 t, %1; cvt.u32.u64 %0, t; }" : "=r"(a) : "l"(p));
    return a;
}
__device__ __forceinline__ void cp_async16(uint32_t s, const void* g) {
    asm volatile("cp.async.cg.shared.global [%0], [%1], 16;\n" :: "r"(s), "l"(g));
}
__device__ __forceinline__ void cp_commit() {
    asm volatile("cp.async.commit_group;\n" ::: "memory");
}
__device__ __forceinline__ void mma_f16(float* c, const uint32_t* a, const uint32_t* b) {
    asm volatile(
        "mma.sync.aligned.m16n8k16.row.col.f32.f16.f16.f32 "
        "{%0,%1,%2,%3}, {%4,%5,%6,%7}, {%8,%9}, {%0,%1,%2,%3};"
        : "+f"(c[0]), "+f"(c[1]), "+f"(c[2]), "+f"(c[3])
        : "r"(a[0]), "r"(a[1]), "r"(a[2]), "r"(a[3]), "r"(b[0]), "r"(b[1]));
}
__device__ __forceinline__ void ldmx4(uint32_t* r, uint32_t addr) {
    asm volatile("ldmatrix.sync.aligned.m8n8.x4.shared.b16 {%0,%1,%2,%3}, [%4];"
        : "=r"(r[0]), "=r"(r[1]), "=r"(r[2]), "=r"(r[3]) : "r"(addr));
}
__device__ __forceinline__ void ldmx2(uint32_t* r, uint32_t addr) {
    asm volatile("ldmatrix.sync.aligned.m8n8.x2.shared.b16 {%0,%1}, [%2];"
        : "=r"(r[0]), "=r"(r[1]) : "r"(addr));
}
__device__ __forceinline__ void ldmx2t(uint32_t* r, uint32_t addr) {
    asm volatile("ldmatrix.sync.aligned.m8n8.x2.trans.shared.b16 {%0,%1}, [%2];"
        : "=r"(r[0]), "=r"(r[1]) : "r"(addr));
}

// ---------------------------------------------------------------------------
// fp16 mma GEMM config (R6/R12 proven — FROZEN):
// CTA 128x128, 8 warps (warp tile 64x32), BK=64, 3-stage cp.async.
// ---------------------------------------------------------------------------
#define STAGES    3
#define AT_BYTES  16384
#define STAGE_SZ  32768
#define GEMM_SMEM (STAGES * STAGE_SZ)

#define GEMM_MAINLOOP(A, Bt, K)                                                  \
    const uint32_t sbase = smem_u32(smem);                                       \
    const int tid  = threadIdx.x;                                                \
    const int wid  = tid >> 5;                                                   \
    const int lane = tid & 31;                                                   \
    const int g    = lane >> 2;                                                  \
    const int t4   = lane & 3;                                                   \
    const int M0 = blockIdx.y * 128;                                             \
    const int N0 = blockIdx.x * 128;                                             \
    const int wm0 = (wid >> 2) * 64;                                             \
    const int wn0 = (wid & 3) * 32;                                              \
    const int iters = (K) >> 6;                                                  \
    const int a_lrow  = (lane & 7) + 8 * ((lane >> 3) & 1);                      \
    const int a_colhi = lane >> 4;                                               \
    const int a_xor   = a_lrow & 7;                                              \
    const int b_lrow  = lane & 7;                                                \
    const int b_chi   = (lane >> 3) & 1;                                         \
    auto load_stage = [&](int s, int k0) {                                       \
        const uint32_t sA = sbase + s * STAGE_SZ;                                \
        const uint32_t sB = sA + AT_BYTES;                                       \
        _Pragma("unroll")                                                        \
        for (int i = 0; i < 4; i++) {                                            \
            const int c = tid + 256 * i;                                         \
            const int r = c >> 3, cc = c & 7;                                    \
            cp_async16(sA + (uint32_t)(r * 128 + ((cc ^ (r & 7)) * 16)),         \
                       (A) + (size_t)(M0 + r) * (K) + k0 + cc * 8);              \
        }                                                                        \
        _Pragma("unroll")                                                        \
        for (int i = 0; i < 4; i++) {                                            \
            const int c = tid + 256 * i;                                         \
            const int r = c >> 3, cc = c & 7;                                    \
            cp_async16(sB + (uint32_t)(r * 128 + ((cc ^ (r & 7)) * 16)),         \
                       (Bt) + (size_t)(N0 + r) * (K) + k0 + cc * 8);             \
        }                                                                        \
        cp_commit();                                                             \
    };                                                                           \
    float acc[4][4][4];                                                          \
    _Pragma("unroll")                                                            \
    for (int mf = 0; mf < 4; mf++)                                               \
        _Pragma("unroll")                                                        \
        for (int nf = 0; nf < 4; nf++)                                           \
            _Pragma("unroll")                                                    \
            for (int r = 0; r < 4; r++) acc[mf][nf][r] = 0.f;                    \
    load_stage(0, 0);                                                            \
    load_stage(1, 64);                                                           \
    for (int it = 0; it < iters; it++) {                                         \
        asm volatile("cp.async.wait_group 1;\n" ::: "memory");                   \
        __syncthreads();                                                         \
        if (it + 2 < iters) load_stage((it + 2) % STAGES, (it + 2) * 64);        \
        else                cp_commit();                                         \
        const uint32_t sA = sbase + (it % STAGES) * STAGE_SZ;                    \
        const uint32_t sB = sA + AT_BYTES;                                       \
        _Pragma("unroll")                                                        \
        for (int ks = 0; ks < 4; ks++) {                                         \
            uint32_t af[4][4], bf[4][2];                                         \
            _Pragma("unroll")                                                    \
            for (int mf = 0; mf < 4; mf++) {                                     \
                const uint32_t adr = sA                                          \
                    + (uint32_t)((wm0 + mf * 16 + a_lrow) * 128                  \
                                 + (((2 * ks + a_colhi) ^ a_xor) * 16));         \
                ldmx4(af[mf], adr);                                              \
            }                                                                    \
            _Pragma("unroll")                                                    \
            for (int nf = 0; nf < 4; nf++) {                                     \
                const uint32_t badr = sB                                         \
                    + (uint32_t)((wn0 + nf * 8 + b_lrow) * 128                   \
                                 + (((2 * ks + b_chi) ^ (b_lrow & 7)) * 16));    \
                ldmx2(bf[nf], badr);                                             \
            }                                                                    \
            _Pragma("unroll")                                                    \
            for (int mf = 0; mf < 4; mf++)                                       \
                _Pragma("unroll")                                                \
                for (int nf = 0; nf < 4; nf++)                                   \
                    mma_f16(acc[mf][nf], af[mf], bf[nf]);                        \
        }                                                                        \
    }

// Generic epilogue GEMM. EPI: 0=bias->f32, 1=bias+res->f32, 2=bias+gelu->half
template <int EPI>
__global__ void __launch_bounds__(256, 2)
mma_gemm(const __half* __restrict__ A, const __half* __restrict__ Bt,
         const float* __restrict__ bias, const float* __restrict__ Res,
         void* __restrict__ Cout, int M, int N, int K) {
    extern __shared__ char smem[];
    GEMM_MAINLOOP(A, Bt, K)

    #pragma unroll
    for (int mf = 0; mf < 4; mf++) {
        #pragma unroll
        for (int nf = 0; nf < 4; nf++) {
            const int col  = N0 + wn0 + nf * 8 + t4 * 2;
            const int row0 = M0 + wm0 + mf * 16 + g;
            const float b0 = bias[col], b1 = bias[col + 1];
            #pragma unroll
            for (int half_i = 0; half_i < 2; half_i++) {
                const int row = row0 + half_i * 8;
                float v0 = acc[mf][nf][half_i * 2 + 0] + b0;
                float v1 = acc[mf][nf][half_i * 2 + 1] + b1;
                if (EPI == 1) {
                    const float2 rv = *(const float2*)(Res + (size_t)row * N + col);
                    v0 += rv.x; v1 += rv.y;
                }
                if (EPI == 2) {
                    float u0 = 0.7978845608028654f * (v0 + 0.044715f * v0 * v0 * v0);
                    float u1 = 0.7978845608028654f * (v1 + 0.044715f * v1 * v1 * v1);
                    v0 = 0.5f * v0 * (1.0f + tanhf(u0));
                    v1 = 0.5f * v1 * (1.0f + tanhf(u1));
                    *(__half2*)((__half*)Cout + (size_t)row * N + col) =
                        __floats2half2_rn(v0, v1);
                } else {
                    *(float2*)((float*)Cout + (size_t)row * N + col) =
                        make_float2(v0, v1);
                }
            }
        }
    }
}

// QKV GEMM with fused RoPE epilogue -> per-head half Q/K/V buffers.
__global__ void __launch_bounds__(256, 2)
mma_gemm_qkv(const __half* __restrict__ A, const __half* __restrict__ Bt,
             const float* __restrict__ bias,
             __half* __restrict__ Qh, __half* __restrict__ Kh,
             __half* __restrict__ Vh, int K) {
    extern __shared__ char smem[];
    GEMM_MAINLOOP(A, Bt, K)

    #pragma unroll
    for (int nf = 0; nf < 4; nf++) {
        const int col = N0 + wn0 + nf * 8 + t4 * 2;     // even column
        const int sec = col >> 10;                       // 0=q 1=k 2=v
        const int d   = col & 1023;
        const int hh  = d >> 6;
        const int dd  = d & 63;
        const int ip  = dd >> 1;                         // rope pair index
        const float invfreq = exp2f((float)ip * -0.41524101186092029f);
        const float b0 = bias[col], b1 = bias[col + 1];
        #pragma unroll
        for (int mf = 0; mf < 4; mf++) {
            #pragma unroll
            for (int half_i = 0; half_i < 2; half_i++) {
                const int row = M0 + wm0 + mf * 16 + g + half_i * 8;
                const int pos = row & (SEQ - 1);
                const int bb  = row >> 10;
                const size_t o = ((size_t)(bb * NHEAD + hh) * SEQ + pos) * 64 + dd;
                float v0 = acc[mf][nf][half_i * 2 + 0] + b0;
                float v1 = acc[mf][nf][half_i * 2 + 1] + b1;
                if (sec == 2) {
                    *(__half2*)&Vh[o] = __floats2half2_rn(v0, v1);
                } else {
                    float sn, cs;
                    sincosf((float)pos * invfreq, &sn, &cs);
                    const float r0 = v0 * cs - v1 * sn;
                    const float r1 = v1 * cs + v0 * sn;
                    if (sec == 0)
                        *(__half2*)&Qh[o] = __floats2half2_rn(r0 * 0.125f, r1 * 0.125f);
                    else
                        *(__half2*)&Kh[o] = __floats2half2_rn(r0, r1);
                }
            }
        }
    }
}

// ---------------------------------------------------------------------------
// Fused weight convert: one launch for all 4 weight tensors (R12 tile body).
// Per-layer tile counts: Wqkv 96x16=1536, Wo 32x16=512, Wfc 128x16=2048,
// Wproj 32x64=2048. Block ranges (x4 layers): [0,6144) [6144,8192)
// [8192,16384) [16384,24576).
// ---------------------------------------------------------------------------
#define CONV_BLOCKS 24576

__global__ void __launch_bounds__(256)
convert_all(const float* __restrict__ Wqkv, const float* __restrict__ Wo,
            const float* __restrict__ Wfc,  const float* __restrict__ Wproj,
            __half* __restrict__ Wqkvh, __half* __restrict__ Woh,
            __half* __restrict__ Wfch,  __half* __restrict__ Wprojh) {
    const int bid = blockIdx.x;
    const float* W; __half* Wh; int K, N, tiles_x, rem;
    if (bid < 6144)       { W = Wqkv;  Wh = Wqkvh;  K = HDIM;  N = 3 * HDIM; tiles_x = 96;  rem = bid; }
    else if (bid < 8192)  { W = Wo;    Wh = Woh;    K = HDIM;  N = HDIM;     tiles_x = 32;  rem = bid - 6144; }
    else if (bid < 16384) { W = Wfc;   Wh = Wfch;   K = HDIM;  N = FFDIM;    tiles_x = 128; rem = bid - 8192; }
    else                  { W = Wproj; Wh = Wprojh; K = FFDIM; N = HDIM;     tiles_x = 32;  rem = bid - 16384; }
    const int per_layer = tiles_x * (K >> 6);
    const int l  = rem / per_layer;
    const int tt = rem - l * per_layer;
    const int n0 = (tt % tiles_x) * 32;
    const int k0 = (tt / tiles_x) * 64;

    __shared__ float t[64][33];
    const float* Wl = W + (size_t)l * K * N;
    __half* Wo_ = Wh + (size_t)l * K * N;
    const int tx = threadIdx.x & 31, ty = threadIdx.x >> 5;   // (32, 8)
    #pragma unroll
    for (int i = 0; i < 64; i += 8)
        t[ty + i][tx] = Wl[(size_t)(k0 + ty + i) * N + n0 + tx];
    __syncthreads();
    #pragma unroll
    for (int i = 0; i < 32; i += 8) {
        const int n = i + ty;
        const __half2 hv = __floats2half2_rn(t[2 * tx][n], t[2 * tx + 1][n]);
        *(__half2*)&Wo_[(size_t)(n0 + n) * K + k0 + 2 * tx] = hv;
    }
}

// ---------------------------------------------------------------------------
// fp16 tensor-core flash attention (causal), heavy-first CTA order (R12).
// CTA = (qtile 64 rows, head*batch), 128 threads (4 warps x 16 q rows).
// ---------------------------------------------------------------------------
#define AQ_OFF 0
#define AK_OFF 8192
#define AK_SZ  8192
#define AV_OFF 24576
#define AV_SZ  8192
#define AP_OFF 40960
#define AP_SZ  2048
#define ATTN_SMEM 49152

__global__ void __launch_bounds__(128)
mma_attn(const __half* __restrict__ Qh, const __half* __restrict__ Kh,
         const __half* __restrict__ Vh, __half* __restrict__ out) {
    extern __shared__ char smc[];
    const uint32_t sbase = smem_u32(smc);
    const int tid = threadIdx.x;
    const int wid = tid >> 5;
    const int lane = tid & 31;
    const int g = lane >> 2;
    const int t4 = lane & 3;

    const int qt = gridDim.x - 1 - blockIdx.x;   // heavy-first
    const int hb = blockIdx.y;
    const int q0 = qt * 64;
    const int ntiles = qt + 1;
    const size_t headbase = (size_t)hb * SEQ * 64;

    const int a_lrow  = (lane & 7) + 8 * ((lane >> 3) & 1);
    const int a_colhi = lane >> 4;
    const int a_xor   = a_lrow & 7;
    const int b_lrow  = lane & 7;
    const int b_chi   = (lane >> 3) & 1;
    const int vl      = lane & 15;

    auto load_tile = [&](uint32_t dst, const __half* src) {
        #pragma unroll
        for (int i = 0; i < 4; i++) {
            const int c = tid + 128 * i;
            const int r = c >> 3, ch = c & 7;
            cp_async16(dst + (uint32_t)(r * 128 + ((ch ^ (r & 7)) * 16)),
                       src + r * 64 + ch * 8);
        }
    };

    load_tile(sbase + AQ_OFF, Qh + headbase + (size_t)q0 * 64);
    load_tile(sbase + AK_OFF, Kh + headbase);
    load_tile(sbase + AV_OFF, Vh + headbase);
    cp_commit();

    float oacc[8][4];
    #pragma unroll
    for (int nf = 0; nf < 8; nf++)
        #pragma unroll
        for (int r = 0; r < 4; r++) oacc[nf][r] = 0.f;
    float m0 = -1e30f, m1 = -1e30f, l0 = 0.f, l1 = 0.f;

    const int qr0 = q0 + 16 * wid + g;

    for (int t = 0; t < ntiles; t++) {
        asm volatile("cp.async.wait_group 0;\n" ::: "memory");
        __syncthreads();

        if (t + 1 < ntiles) {
            const size_t kvoff = headbase + (size_t)(t + 1) * 64 * 64;
            load_tile(sbase + AK_OFF + ((t + 1) & 1) * AK_SZ, Kh + kvoff);
            load_tile(sbase + AV_OFF + ((t + 1) & 1) * AV_SZ, Vh + kvoff);
            cp_commit();
        }

        const uint32_t Ks = sbase + AK_OFF + (t & 1) * AK_SZ;
        const uint32_t Vs = sbase + AV_OFF + (t & 1) * AV_SZ;
        const uint32_t Qs = sbase + AQ_OFF;
        const uint32_t Pw = sbase + AP_OFF + wid * AP_SZ;

        float sacc[8][4];
        #pragma unroll
        for (int nf = 0; nf < 8; nf++)
            #pragma unroll
            for (int r = 0; r < 4; r++) sacc[nf][r] = 0.f;

        #pragma unroll
        for (int ks = 0; ks < 4; ks++) {
            uint32_t af[4];
            ldmx4(af, Qs + (uint32_t)((16 * wid + a_lrow) * 128
                                      + (((2 * ks + a_colhi) ^ a_xor) * 16)));
            #pragma unroll
            for (int nf = 0; nf < 8; nf++) {
                uint32_t bf[2];
                ldmx2(bf, Ks + (uint32_t)((nf * 8 + b_lrow) * 128
                                          + (((2 * ks + b_chi) ^ (b_lrow & 7)) * 16)));
                mma_f16(sacc[nf], af, bf);
            }
        }

        const bool diag = (t == ntiles - 1);
        float mx0 = -1e30f, mx1 = -1e30f;
        #pragma unroll
        for (int nf = 0; nf < 8; nf++) {
            if (diag) {
                const int j = t * 64 + 8 * nf + 2 * t4;
                if (j     > qr0)     sacc[nf][0] = -1e30f;
                if (j + 1 > qr0)     sacc[nf][1] = -1e30f;
                if (j     > qr0 + 8) sacc[nf][2] = -1e30f;
                if (j + 1 > qr0 + 8) sacc[nf][3] = -1e30f;
            }
            mx0 = fmaxf(mx0, fmaxf(sacc[nf][0], sacc[nf][1]));
            mx1 = fmaxf(mx1, fmaxf(sacc[nf][2], sacc[nf][3]));
        }
        mx0 = fmaxf(mx0, __shfl_xor_sync(0xffffffffu, mx0, 1));
        mx0 = fmaxf(mx0, __shfl_xor_sync(0xffffffffu, mx0, 2));
        mx1 = fmaxf(mx1, __shfl_xor_sync(0xffffffffu, mx1, 1));
        mx1 = fmaxf(mx1, __shfl_xor_sync(0xffffffffu, mx1, 2));

        const float mn0 = fmaxf(m0, mx0);
        const float mn1 = fmaxf(m1, mx1);
        const float c0 = __expf(m0 - mn0);
        const float c1 = __expf(m1 - mn1);
        float sum0 = 0.f, sum1 = 0.f;
        #pragma unroll
        for (int nf = 0; nf < 8; nf++) {
            sacc[nf][0] = __expf(sacc[nf][0] - mn0);
            sacc[nf][1] = __expf(sacc[nf][1] - mn0);
            sacc[nf][2] = __expf(sacc[nf][2] - mn1);
            sacc[nf][3] = __expf(sacc[nf][3] - mn1);
            sum0 += sacc[nf][0] + sacc[nf][1];
            sum1 += sacc[nf][2] + sacc[nf][3];
        }
        sum0 += __shfl_xor_sync(0xffffffffu, sum0, 1);
        sum0 += __shfl_xor_sync(0xffffffffu, sum0, 2);
        sum1 += __shfl_xor_sync(0xffffffffu, sum1, 1);
        sum1 += __shfl_xor_sync(0xffffffffu, sum1, 2);
        l0 = l0 * c0 + sum0;
        l1 = l1 * c1 + sum1;
        m0 = mn0; m1 = mn1;

        #pragma unroll
        for (int nf = 0; nf < 8; nf++) {
            oacc[nf][0] *= c0; oacc[nf][1] *= c0;
            oacc[nf][2] *= c1; oacc[nf][3] *= c1;
            const uint32_t p0 = Pw + (uint32_t)(g * 128 + ((nf ^ (g & 7)) * 16) + t4 * 4);
            const uint32_t p1 = Pw + (uint32_t)((g + 8) * 128 + ((nf ^ ((g + 8) & 7)) * 16) + t4 * 4);
            *(__half2*)(smc + (p0 - sbase)) = __floats2half2_rn(sacc[nf][0], sacc[nf][1]);
            *(__half2*)(smc + (p1 - sbase)) = __floats2half2_rn(sacc[nf][2], sacc[nf][3]);
        }
        __syncwarp();

        #pragma unroll
        for (int ks = 0; ks < 4; ks++) {
            uint32_t af[4];
            ldmx4(af, Pw + (uint32_t)(a_lrow * 128
                                      + (((2 * ks + a_colhi) ^ a_xor) * 16)));
            const int vrow = 16 * ks + vl;
            #pragma unroll
            for (int nf = 0; nf < 8; nf++) {
                uint32_t bf[2];
                ldmx2t(bf, Vs + (uint32_t)(vrow * 128 + ((nf ^ (vrow & 7)) * 16)));
                mma_f16(oacc[nf], af, bf);
            }
        }
    }

    const float inv0 = 1.0f / l0;
    const float inv1 = 1.0f / l1;
    const int h = hb & (NHEAD - 1);
    const int b = hb >> 4;
    const size_t row0 = (size_t)b * SEQ + q0 + 16 * wid + g;
    #pragma unroll
    for (int nf = 0; nf < 8; nf++) {
        const int col = h * 64 + 8 * nf + 2 * t4;
        *(__half2*)&out[row0 * HDIM + col] =
            __floats2half2_rn(oacc[nf][0] * inv0, oacc[nf][1] * inv0);
        *(__half2*)&out[(row0 + 8) * HDIM + col] =
            __floats2half2_rn(oacc[nf][2] * inv1, oacc[nf][3] * inv1);
    }
}

// ---------------------------------------------------------------------------
// LayerNorm: one warp per row, one-pass moments.
// ---------------------------------------------------------------------------
template <int HALF_OUT>
__global__ void __launch_bounds__(256)
ln_kernel(const float* __restrict__ x, const float* __restrict__ gamma,
          const float* __restrict__ beta, void* __restrict__ yv) {
    const int warp = threadIdx.x >> 5;
    const int lane = threadIdx.x & 31;
    const int row = blockIdx.x * 8 + warp;
    const float* xr = x + (size_t)row * HDIM;

    float4 v[8];
    float s = 0.f, s2 = 0.f;
    #pragma unroll
    for (int j = 0; j < 8; j++) {
        v[j] = *(const float4*)(xr + lane * 4 + j * 128);
        s  += v[j].x + v[j].y + v[j].z + v[j].w;
        s2 += v[j].x * v[j].x + v[j].y * v[j].y
            + v[j].z * v[j].z + v[j].w * v[j].w;
    }
    #pragma unroll
    for (int off = 16; off; off >>= 1) {
        s  += __shfl_xor_sync(0xffffffffu, s,  off);
        s2 += __shfl_xor_sync(0xffffffffu, s2, off);
    }
    const float mean = s * (1.0f / HDIM);
    const float var  = s2 * (1.0f / HDIM) - mean * mean;
    const float rs   = rsqrtf(var + 1e-5f);

    #pragma unroll
    for (int j = 0; j < 8; j++) {
        const int ci = lane * 4 + j * 128;
        const float4 gv = *(const float4*)(gamma + ci);
        const float4 bv = *(const float4*)(beta + ci);
        const float o0 = (v[j].x - mean) * rs * gv.x + bv.x;
        const float o1 = (v[j].y - mean) * rs * gv.y + bv.y;
        const float o2 = (v[j].z - mean) * rs * gv.z + bv.z;
        const float o3 = (v[j].w - mean) * rs * gv.w + bv.w;
        if (HALF_OUT) {
            __half2 h01 = __floats2half2_rn(o0, o1);
            __half2 h23 = __floats2half2_rn(o2, o3);
            uint2 pk;
            pk.x = *(uint32_t*)&h01;
            pk.y = *(uint32_t*)&h23;
            *(uint2*)((__half*)yv + (size_t)row * HDIM + ci) = pk;
        } else {
            *(float4*)((float*)yv + (size_t)row * HDIM + ci) =
                make_float4(o0, o1, o2, o3);
        }
    }
}

// ---------------------------------------------------------------------------
// Launch
// ---------------------------------------------------------------------------
extern "C" void kernel_launch(void* const* d_in, const int* in_sizes, int n_in,
                              void* d_out, int out_size) {
    const float* embeds = (const float*)d_in[0];
    const float* Wqkv  = (const float*)d_in[2];
    const float* bqkv  = (const float*)d_in[3];
    const float* Wo    = (const float*)d_in[4];
    const float* bo    = (const float*)d_in[5];
    const float* ln1g  = (const float*)d_in[6];
    const float* ln1b  = (const float*)d_in[7];
    const float* ln2g  = (const float*)d_in[8];
    const float* ln2b  = (const float*)d_in[9];
    const float* Wfc   = (const float*)d_in[10];
    const float* bfc   = (const float*)d_in[11];
    const float* Wproj = (const float*)d_in[12];
    const float* bproj = (const float*)d_in[13];
    const float* lnfg  = (const float*)d_in[14];
    const float* lnfb  = (const float*)d_in[15];

    float *h;
    __half *xh, *attnh, *fch, *qh, *kh, *vh, *Wqkvh, *Woh, *Wfch, *Wprojh;
    cudaGetSymbolAddress((void**)&h,      g_h);
    cudaGetSymbolAddress((void**)&xh,     g_xh);
    cudaGetSymbolAddress((void**)&attnh,  g_attnh);
    cudaGetSymbolAddress((void**)&fch,    g_fch);
    cudaGetSymbolAddress((void**)&qh,     g_qheads);
    cudaGetSymbolAddress((void**)&kh,     g_kheads);
    cudaGetSymbolAddress((void**)&vh,     g_vheads);
    cudaGetSymbolAddress((void**)&Wqkvh,  g_Wqkvh);
    cudaGetSymbolAddress((void**)&Woh,    g_Woh);
    cudaGetSymbolAddress((void**)&Wfch,   g_Wfch);
    cudaGetSymbolAddress((void**)&Wprojh, g_Wprojh);

    cudaFuncSetAttribute(mma_gemm<0>, cudaFuncAttributeMaxDynamicSharedMemorySize, GEMM_SMEM);
    cudaFuncSetAttribute(mma_gemm<1>, cudaFuncAttributeMaxDynamicSharedMemorySize, GEMM_SMEM);
    cudaFuncSetAttribute(mma_gemm<2>, cudaFuncAttributeMaxDynamicSharedMemorySize, GEMM_SMEM);
    cudaFuncSetAttribute(mma_gemm_qkv, cudaFuncAttributeMaxDynamicSharedMemorySize, GEMM_SMEM);
    cudaFuncSetAttribute(mma_attn,     cudaFuncAttributeMaxDynamicSharedMemorySize, ATTN_SMEM);

    convert_all<<<CONV_BLOCKS, 256>>>(Wqkv, Wo, Wfc, Wproj,
                                      Wqkvh, Woh, Wfch, Wprojh);

    for (int l = 0; l < NLAYER; l++) {
        const float* hin = (l == 0) ? embeds : h;
        ln_kernel<1><<<MTOK / 8, 256>>>(hin, ln1g + l * HDIM, ln1b + l * HDIM, xh);
        mma_gemm_qkv<<<dim3(3 * HDIM / 128, MTOK / 128), 256, GEMM_SMEM>>>(
            xh, Wqkvh + (size_t)l * HDIM * 3 * HDIM, bqkv + (size_t)l * 3 * HDIM,
            qh, kh, vh, HDIM);
        mma_attn<<<dim3(SEQ / 64, BATCH * NHEAD), 128, ATTN_SMEM>>>(qh, kh, vh, attnh);
        mma_gemm<1><<<dim3(HDIM / 128, MTOK / 128), 256, GEMM_SMEM>>>(
            attnh, Woh + (size_t)l * HDIM * HDIM, bo + (size_t)l * HDIM,
            hin, h, MTOK, HDIM, HDIM);
        ln_kernel<1><<<MTOK / 8, 256>>>(h, ln2g + l * HDIM, ln2b + l * HDIM, xh);
        mma_gemm<2><<<dim3(FFDIM / 128, MTOK / 128), 256, GEMM_SMEM>>>(
            xh, Wfch + (size_t)l * HDIM * FFDIM, bfc + (size_t)l * FFDIM,
            nullptr, fch, MTOK, FFDIM, HDIM);
        mma_gemm<1><<<dim3(HDIM / 128, MTOK / 128), 256, GEMM_SMEM>>>(
            fch, Wprojh + (size_t)l * FFDIM * HDIM, bproj + (size_t)l * HDIM,
            h, h, MTOK, HDIM, FFDIM);
    }
    ln_kernel<0><<<MTOK / 8, 256>>>(h, lnfg, lnfb, d_out);
}

// round 17
// speedup vs baseline: 1.0810x; 1.0003x over previous
#include <cuda_runtime.h>
#include <cuda_fp16.h>
#include <math.h>
#include <stdint.h>

// Problem constants
#define NLAYER 4
#define HDIM   1024
#define NHEAD  16
#define HEADD  64
#define FFDIM  4096
#define BATCH  4
#define SEQ    1024
#define MTOK   (BATCH * SEQ)   // 4096 tokens

// ---------------------------------------------------------------------------
// Scratch (allocation-free: __device__ globals)
// ---------------------------------------------------------------------------
__device__ float g_h   [MTOK * HDIM];
__device__ __align__(16) __half g_xh   [MTOK * HDIM];
__device__ __align__(16) __half g_attnh[MTOK * HDIM];
__device__ __align__(16) __half g_fch  [MTOK * FFDIM];
// Per-head Q/K/V, layout [b*NH][S][64] half
__device__ __align__(16) __half g_qheads[MTOK * HDIM];
__device__ __align__(16) __half g_kheads[MTOK * HDIM];
__device__ __align__(16) __half g_vheads[MTOK * HDIM];
// Converted weights, layout [l][N][K] half
__device__ __align__(16) __half g_Wqkvh [NLAYER * 3 * HDIM * HDIM];
__device__ __align__(16) __half g_Woh   [NLAYER * HDIM * HDIM];
__device__ __align__(16) __half g_Wfch  [NLAYER * HDIM * FFDIM];
__device__ __align__(16) __half g_Wprojh[NLAYER * FFDIM * HDIM];

// ---------------------------------------------------------------------------
// PTX helpers
// ---------------------------------------------------------------------------
__device__ __forceinline__ uint32_t smem_u32(const void* p) {
    uint32_t a;
    asm("{ .reg .u64 t; cvta.to.shared.u64 t, %1; cvt.u32.u64 %0, t; }" : "=r"(a) : "l"(p));
    return a;
}
__device__ __forceinline__ void cp_async16(uint32_t s, const void* g) {
    asm volatile("cp.async.cg.shared.global [%0], [%1], 16;\n" :: "r"(s), "l"(g));
}
__device__ __forceinline__ void cp_commit() {
    asm volatile("cp.async.commit_group;\n" ::: "memory");
}
__device__ __forceinline__ void mma_f16(float* c, const uint32_t* a, const uint32_t* b) {
    asm volatile(
        "mma.sync.aligned.m16n8k16.row.col.f32.f16.f16.f32 "
        "{%0,%1,%2,%3}, {%4,%5,%6,%7}, {%8,%9}, {%0,%1,%2,%3};"
        : "+f"(c[0]), "+f"(c[1]), "+f"(c[2]), "+f"(c[3])
        : "r"(a[0]), "r"(a[1]), "r"(a[2]), "r"(a[3]), "r"(b[0]), "r"(b[1]));
}
__device__ __forceinline__ void ldmx4(uint32_t* r, uint32_t addr) {
    asm volatile("ldmatrix.sync.aligned.m8n8.x4.shared.b16 {%0,%1,%2,%3}, [%4];"
        : "=r"(r[0]), "=r"(r[1]), "=r"(r[2]), "=r"(r[3]) : "r"(addr));
}
__device__ __forceinline__ void ldmx2(uint32_t* r, uint32_t addr) {
    asm volatile("ldmatrix.sync.aligned.m8n8.x2.shared.b16 {%0,%1}, [%2];"
        : "=r"(r[0]), "=r"(r[1]) : "r"(addr));
}
__device__ __forceinline__ void ldmx2t(uint32_t* r, uint32_t addr) {
    asm volatile("ldmatrix.sync.aligned.m8n8.x2.trans.shared.b16 {%0,%1}, [%2];"
        : "=r"(r[0]), "=r"(r[1]) : "r"(addr));
}

// ---------------------------------------------------------------------------
// fp16 mma GEMM config (R6/R12 proven — FROZEN):
// CTA 128x128, 8 warps (warp tile 64x32), BK=64, 3-stage cp.async.
// ---------------------------------------------------------------------------
#define STAGES    3
#define AT_BYTES  16384
#define STAGE_SZ  32768
#define GEMM_SMEM (STAGES * STAGE_SZ)

#define GEMM_MAINLOOP(A, Bt, K)                                                  \
    const uint32_t sbase = smem_u32(smem);                                       \
    const int tid  = threadIdx.x;                                                \
    const int wid  = tid >> 5;                                                   \
    const int lane = tid & 31;                                                   \
    const int g    = lane >> 2;                                                  \
    const int t4   = lane & 3;                                                   \
    const int M0 = blockIdx.y * 128;                                             \
    const int N0 = blockIdx.x * 128;                                             \
    const int wm0 = (wid >> 2) * 64;                                             \
    const int wn0 = (wid & 3) * 32;                                              \
    const int iters = (K) >> 6;                                                  \
    const int a_lrow  = (lane & 7) + 8 * ((lane >> 3) & 1);                      \
    const int a_colhi = lane >> 4;                                               \
    const int a_xor   = a_lrow & 7;                                              \
    const int b_lrow  = lane & 7;                                                \
    const int b_chi   = (lane >> 3) & 1;                                         \
    auto load_stage = [&](int s, int k0) {                                       \
        const uint32_t sA = sbase + s * STAGE_SZ;                                \
        const uint32_t sB = sA + AT_BYTES;                                       \
        _Pragma("unroll")                                                        \
        for (int i = 0; i < 4; i++) {                                            \
            const int c = tid + 256 * i;                                         \
            const int r = c >> 3, cc = c & 7;                                    \
            cp_async16(sA + (uint32_t)(r * 128 + ((cc ^ (r & 7)) * 16)),         \
                       (A) + (size_t)(M0 + r) * (K) + k0 + cc * 8);              \
        }                                                                        \
        _Pragma("unroll")                                                        \
        for (int i = 0; i < 4; i++) {                                            \
            const int c = tid + 256 * i;                                         \
            const int r = c >> 3, cc = c & 7;                                    \
            cp_async16(sB + (uint32_t)(r * 128 + ((cc ^ (r & 7)) * 16)),         \
                       (Bt) + (size_t)(N0 + r) * (K) + k0 + cc * 8);             \
        }                                                                        \
        cp_commit();                                                             \
    };                                                                           \
    float acc[4][4][4];                                                          \
    _Pragma("unroll")                                                            \
    for (int mf = 0; mf < 4; mf++)                                               \
        _Pragma("unroll")                                                        \
        for (int nf = 0; nf < 4; nf++)                                           \
            _Pragma("unroll")                                                    \
            for (int r = 0; r < 4; r++) acc[mf][nf][r] = 0.f;                    \
    load_stage(0, 0);                                                            \
    load_stage(1, 64);                                                           \
    for (int it = 0; it < iters; it++) {                                         \
        asm volatile("cp.async.wait_group 1;\n" ::: "memory");                   \
        __syncthreads();                                                         \
        if (it + 2 < iters) load_stage((it + 2) % STAGES, (it + 2) * 64);        \
        else                cp_commit();                                         \
        const uint32_t sA = sbase + (it % STAGES) * STAGE_SZ;                    \
        const uint32_t sB = sA + AT_BYTES;                                       \
        _Pragma("unroll")                                                        \
        for (int ks = 0; ks < 4; ks++) {                                         \
            uint32_t af[4][4], bf[4][2];                                         \
            _Pragma("unroll")                                                    \
            for (int mf = 0; mf < 4; mf++) {                                     \
                const uint32_t adr = sA                                          \
                    + (uint32_t)((wm0 + mf * 16 + a_lrow) * 128                  \
                                 + (((2 * ks + a_colhi) ^ a_xor) * 16));         \
                ldmx4(af[mf], adr);                                              \
            }                                                                    \
            _Pragma("unroll")                                                    \
            for (int nf = 0; nf < 4; nf++) {                                     \
                const uint32_t badr = sB                                         \
                    + (uint32_t)((wn0 + nf * 8 + b_lrow) * 128                   \
                                 + (((2 * ks + b_chi) ^ (b_lrow & 7)) * 16));    \
                ldmx2(bf[nf], badr);                                             \
            }                                                                    \
            _Pragma("unroll")                                                    \
            for (int mf = 0; mf < 4; mf++)                                       \
                _Pragma("unroll")                                                \
                for (int nf = 0; nf < 4; nf++)                                   \
                    mma_f16(acc[mf][nf], af[mf], bf[nf]);                        \
        }                                                                        \
    }

// Generic epilogue GEMM. EPI: 0=bias->f32, 1=bias+res->f32, 2=bias+gelu->half
template <int EPI>
__global__ void __launch_bounds__(256, 2)
mma_gemm(const __half* __restrict__ A, const __half* __restrict__ Bt,
         const float* __restrict__ bias, const float* __restrict__ Res,
         void* __restrict__ Cout, int M, int N, int K) {
    extern __shared__ char smem[];
    GEMM_MAINLOOP(A, Bt, K)

    #pragma unroll
    for (int mf = 0; mf < 4; mf++) {
        #pragma unroll
        for (int nf = 0; nf < 4; nf++) {
            const int col  = N0 + wn0 + nf * 8 + t4 * 2;
            const int row0 = M0 + wm0 + mf * 16 + g;
            const float b0 = bias[col], b1 = bias[col + 1];
            #pragma unroll
            for (int half_i = 0; half_i < 2; half_i++) {
                const int row = row0 + half_i * 8;
                float v0 = acc[mf][nf][half_i * 2 + 0] + b0;
                float v1 = acc[mf][nf][half_i * 2 + 1] + b1;
                if (EPI == 1) {
                    const float2 rv = *(const float2*)(Res + (size_t)row * N + col);
                    v0 += rv.x; v1 += rv.y;
                }
                if (EPI == 2) {
                    float u0 = 0.7978845608028654f * (v0 + 0.044715f * v0 * v0 * v0);
                    float u1 = 0.7978845608028654f * (v1 + 0.044715f * v1 * v1 * v1);
                    v0 = 0.5f * v0 * (1.0f + tanhf(u0));
                    v1 = 0.5f * v1 * (1.0f + tanhf(u1));
                    *(__half2*)((__half*)Cout + (size_t)row * N + col) =
                        __floats2half2_rn(v0, v1);
                } else {
                    *(float2*)((float*)Cout + (size_t)row * N + col) =
                        make_float2(v0, v1);
                }
            }
        }
    }
}

// QKV GEMM with fused RoPE epilogue -> per-head half Q/K/V buffers.
__global__ void __launch_bounds__(256, 2)
mma_gemm_qkv(const __half* __restrict__ A, const __half* __restrict__ Bt,
             const float* __restrict__ bias,
             __half* __restrict__ Qh, __half* __restrict__ Kh,
             __half* __restrict__ Vh, int K) {
    extern __shared__ char smem[];
    GEMM_MAINLOOP(A, Bt, K)

    #pragma unroll
    for (int nf = 0; nf < 4; nf++) {
        const int col = N0 + wn0 + nf * 8 + t4 * 2;     // even column
        const int sec = col >> 10;                       // 0=q 1=k 2=v
        const int d   = col & 1023;
        const int hh  = d >> 6;
        const int dd  = d & 63;
        const int ip  = dd >> 1;                         // rope pair index
        const float invfreq = exp2f((float)ip * -0.41524101186092029f);
        const float b0 = bias[col], b1 = bias[col + 1];
        #pragma unroll
        for (int mf = 0; mf < 4; mf++) {
            #pragma unroll
            for (int half_i = 0; half_i < 2; half_i++) {
                const int row = M0 + wm0 + mf * 16 + g + half_i * 8;
                const int pos = row & (SEQ - 1);
                const int bb  = row >> 10;
                const size_t o = ((size_t)(bb * NHEAD + hh) * SEQ + pos) * 64 + dd;
                float v0 = acc[mf][nf][half_i * 2 + 0] + b0;
                float v1 = acc[mf][nf][half_i * 2 + 1] + b1;
                if (sec == 2) {
                    *(__half2*)&Vh[o] = __floats2half2_rn(v0, v1);
                } else {
                    float sn, cs;
                    sincosf((float)pos * invfreq, &sn, &cs);
                    const float r0 = v0 * cs - v1 * sn;
                    const float r1 = v1 * cs + v0 * sn;
                    if (sec == 0)
                        *(__half2*)&Qh[o] = __floats2half2_rn(r0 * 0.125f, r1 * 0.125f);
                    else
                        *(__half2*)&Kh[o] = __floats2half2_rn(r0, r1);
                }
            }
        }
    }
}

// ---------------------------------------------------------------------------
// Fused weight convert: one launch for all 4 weight tensors (R12 tile body).
// ---------------------------------------------------------------------------
#define CONV_BLOCKS 24576

__global__ void __launch_bounds__(256)
convert_all(const float* __restrict__ Wqkv, const float* __restrict__ Wo,
            const float* __restrict__ Wfc,  const float* __restrict__ Wproj,
            __half* __restrict__ Wqkvh, __half* __restrict__ Woh,
            __half* __restrict__ Wfch,  __half* __restrict__ Wprojh) {
    const int bid = blockIdx.x;
    const float* W; __half* Wh; int K, N, tiles_x, rem;
    if (bid < 6144)       { W = Wqkv;  Wh = Wqkvh;  K = HDIM;  N = 3 * HDIM; tiles_x = 96;  rem = bid; }
    else if (bid < 8192)  { W = Wo;    Wh = Woh;    K = HDIM;  N = HDIM;     tiles_x = 32;  rem = bid - 6144; }
    else if (bid < 16384) { W = Wfc;   Wh = Wfch;   K = HDIM;  N = FFDIM;    tiles_x = 128; rem = bid - 8192; }
    else                  { W = Wproj; Wh = Wprojh; K = FFDIM; N = HDIM;     tiles_x = 32;  rem = bid - 16384; }
    const int per_layer = tiles_x * (K >> 6);
    const int l  = rem / per_layer;
    const int tt = rem - l * per_layer;
    const int n0 = (tt % tiles_x) * 32;
    const int k0 = (tt / tiles_x) * 64;

    __shared__ float t[64][33];
    const float* Wl = W + (size_t)l * K * N;
    __half* Wo_ = Wh + (size_t)l * K * N;
    const int tx = threadIdx.x & 31, ty = threadIdx.x >> 5;   // (32, 8)
    #pragma unroll
    for (int i = 0; i < 64; i += 8)
        t[ty + i][tx] = Wl[(size_t)(k0 + ty + i) * N + n0 + tx];
    __syncthreads();
    #pragma unroll
    for (int i = 0; i < 32; i += 8) {
        const int n = i + ty;
        const __half2 hv = __floats2half2_rn(t[2 * tx][n], t[2 * tx + 1][n]);
        *(__half2*)&Wo_[(size_t)(n0 + n) * K + k0 + 2 * tx] = hv;
    }
}

// ---------------------------------------------------------------------------
// fp16 tensor-core flash attention (causal), heavy-first CTA order (R12).
// CTA = (qtile 64 rows, head*batch), 128 threads (4 warps x 16 q rows).
// ---------------------------------------------------------------------------
#define AQ_OFF 0
#define AK_OFF 8192
#define AK_SZ  8192
#define AV_OFF 24576
#define AV_SZ  8192
#define AP_OFF 40960
#define AP_SZ  2048
#define ATTN_SMEM 49152

__global__ void __launch_bounds__(128)
mma_attn(const __half* __restrict__ Qh, const __half* __restrict__ Kh,
         const __half* __restrict__ Vh, __half* __restrict__ out) {
    extern __shared__ char smc[];
    const uint32_t sbase = smem_u32(smc);
    const int tid = threadIdx.x;
    const int wid = tid >> 5;
    const int lane = tid & 31;
    const int g = lane >> 2;
    const int t4 = lane & 3;

    const int qt = gridDim.x - 1 - blockIdx.x;   // heavy-first
    const int hb = blockIdx.y;
    const int q0 = qt * 64;
    const int ntiles = qt + 1;
    const size_t headbase = (size_t)hb * SEQ * 64;

    const int a_lrow  = (lane & 7) + 8 * ((lane >> 3) & 1);
    const int a_colhi = lane >> 4;
    const int a_xor   = a_lrow & 7;
    const int b_lrow  = lane & 7;
    const int b_chi   = (lane >> 3) & 1;
    const int vl      = lane & 15;

    auto load_tile = [&](uint32_t dst, const __half* src) {
        #pragma unroll
        for (int i = 0; i < 4; i++) {
            const int c = tid + 128 * i;
            const int r = c >> 3, ch = c & 7;
            cp_async16(dst + (uint32_t)(r * 128 + ((ch ^ (r & 7)) * 16)),
                       src + r * 64 + ch * 8);
        }
    };

    load_tile(sbase + AQ_OFF, Qh + headbase + (size_t)q0 * 64);
    load_tile(sbase + AK_OFF, Kh + headbase);
    load_tile(sbase + AV_OFF, Vh + headbase);
    cp_commit();

    float oacc[8][4];
    #pragma unroll
    for (int nf = 0; nf < 8; nf++)
        #pragma unroll
        for (int r = 0; r < 4; r++) oacc[nf][r] = 0.f;
    float m0 = -1e30f, m1 = -1e30f, l0 = 0.f, l1 = 0.f;

    const int qr0 = q0 + 16 * wid + g;

    for (int t = 0; t < ntiles; t++) {
        asm volatile("cp.async.wait_group 0;\n" ::: "memory");
        __syncthreads();

        if (t + 1 < ntiles) {
            const size_t kvoff = headbase + (size_t)(t + 1) * 64 * 64;
            load_tile(sbase + AK_OFF + ((t + 1) & 1) * AK_SZ, Kh + kvoff);
            load_tile(sbase + AV_OFF + ((t + 1) & 1) * AV_SZ, Vh + kvoff);
            cp_commit();
        }

        const uint32_t Ks = sbase + AK_OFF + (t & 1) * AK_SZ;
        const uint32_t Vs = sbase + AV_OFF + (t & 1) * AV_SZ;
        const uint32_t Qs = sbase + AQ_OFF;
        const uint32_t Pw = sbase + AP_OFF + wid * AP_SZ;

        float sacc[8][4];
        #pragma unroll
        for (int nf = 0; nf < 8; nf++)
            #pragma unroll
            for (int r = 0; r < 4; r++) sacc[nf][r] = 0.f;

        #pragma unroll
        for (int ks = 0; ks < 4; ks++) {
            uint32_t af[4];
            ldmx4(af, Qs + (uint32_t)((16 * wid + a_lrow) * 128
                                      + (((2 * ks + a_colhi) ^ a_xor) * 16)));
            #pragma unroll
            for (int nf = 0; nf < 8; nf++) {
                uint32_t bf[2];
                ldmx2(bf, Ks + (uint32_t)((nf * 8 + b_lrow) * 128
                                          + (((2 * ks + b_chi) ^ (b_lrow & 7)) * 16)));
                mma_f16(sacc[nf], af, bf);
            }
        }

        const bool diag = (t == ntiles - 1);
        float mx0 = -1e30f, mx1 = -1e30f;
        #pragma unroll
        for (int nf = 0; nf < 8; nf++) {
            if (diag) {
                const int j = t * 64 + 8 * nf + 2 * t4;
                if (j     > qr0)     sacc[nf][0] = -1e30f;
                if (j + 1 > qr0)     sacc[nf][1] = -1e30f;
                if (j     > qr0 + 8) sacc[nf][2] = -1e30f;
                if (j + 1 > qr0 + 8) sacc[nf][3] = -1e30f;
            }
            mx0 = fmaxf(mx0, fmaxf(sacc[nf][0], sacc[nf][1]));
            mx1 = fmaxf(mx1, fmaxf(sacc[nf][2], sacc[nf][3]));
        }
        mx0 = fmaxf(mx0, __shfl_xor_sync(0xffffffffu, mx0, 1));
        mx0 = fmaxf(mx0, __shfl_xor_sync(0xffffffffu, mx0, 2));
        mx1 = fmaxf(mx1, __shfl_xor_sync(0xffffffffu, mx1, 1));
        mx1 = fmaxf(mx1, __shfl_xor_sync(0xffffffffu, mx1, 2));

        const float mn0 = fmaxf(m0, mx0);
        const float mn1 = fmaxf(m1, mx1);
        const float c0 = __expf(m0 - mn0);
        const float c1 = __expf(m1 - mn1);
        float sum0 = 0.f, sum1 = 0.f;
        #pragma unroll
        for (int nf = 0; nf < 8; nf++) {
            sacc[nf][0] = __expf(sacc[nf][0] - mn0);
            sacc[nf][1] = __expf(sacc[nf][1] - mn0);
            sacc[nf][2] = __expf(sacc[nf][2] - mn1);
            sacc[nf][3] = __expf(sacc[nf][3] - mn1);
            sum0 += sacc[nf][0] + sacc[nf][1];
            sum1 += sacc[nf][2] + sacc[nf][3];
        }
        sum0 += __shfl_xor_sync(0xffffffffu, sum0, 1);
        sum0 += __shfl_xor_sync(0xffffffffu, sum0, 2);
        sum1 += __shfl_xor_sync(0xffffffffu, sum1, 1);
        sum1 += __shfl_xor_sync(0xffffffffu, sum1, 2);
        l0 = l0 * c0 + sum0;
        l1 = l1 * c1 + sum1;
        m0 = mn0; m1 = mn1;

        #pragma unroll
        for (int nf = 0; nf < 8; nf++) {
            oacc[nf][0] *= c0; oacc[nf][1] *= c0;
            oacc[nf][2] *= c1; oacc[nf][3] *= c1;
            const uint32_t p0 = Pw + (uint32_t)(g * 128 + ((nf ^ (g & 7)) * 16) + t4 * 4);
            const uint32_t p1 = Pw + (uint32_t)((g + 8) * 128 + ((nf ^ ((g + 8) & 7)) * 16) + t4 * 4);
            *(__half2*)(smc + (p0 - sbase)) = __floats2half2_rn(sacc[nf][0], sacc[nf][1]);
            *(__half2*)(smc + (p1 - sbase)) = __floats2half2_rn(sacc[nf][2], sacc[nf][3]);
        }
        __syncwarp();

        #pragma unroll
        for (int ks = 0; ks < 4; ks++) {
            uint32_t af[4];
            ldmx4(af, Pw + (uint32_t)(a_lrow * 128
                                      + (((2 * ks + a_colhi) ^ a_xor) * 16)));
            const int vrow = 16 * ks + vl;
            #pragma unroll
            for (int nf = 0; nf < 8; nf++) {
                uint32_t bf[2];
                ldmx2t(bf, Vs + (uint32_t)(vrow * 128 + ((nf ^ (vrow & 7)) * 16)));
                mma_f16(oacc[nf], af, bf);
            }
        }
    }

    const float inv0 = 1.0f / l0;
    const float inv1 = 1.0f / l1;
    const int h = hb & (NHEAD - 1);
    const int b = hb >> 4;
    const size_t row0 = (size_t)b * SEQ + q0 + 16 * wid + g;
    #pragma unroll
    for (int nf = 0; nf < 8; nf++) {
        const int col = h * 64 + 8 * nf + 2 * t4;
        *(__half2*)&out[row0 * HDIM + col] =
            __floats2half2_rn(oacc[nf][0] * inv0, oacc[nf][1] * inv0);
        *(__half2*)&out[(row0 + 8) * HDIM + col] =
            __floats2half2_rn(oacc[nf][2] * inv1, oacc[nf][3] * inv1);
    }
}

// ---------------------------------------------------------------------------
// LayerNorm: one warp per row, one-pass moments.
// ---------------------------------------------------------------------------
template <int HALF_OUT>
__global__ void __launch_bounds__(256)
ln_kernel(const float* __restrict__ x, const float* __restrict__ gamma,
          const float* __restrict__ beta, void* __restrict__ yv) {
    const int warp = threadIdx.x >> 5;
    const int lane = threadIdx.x & 31;
    const int row = blockIdx.x * 8 + warp;
    const float* xr = x + (size_t)row * HDIM;

    float4 v[8];
    float s = 0.f, s2 = 0.f;
    #pragma unroll
    for (int j = 0; j < 8; j++) {
        v[j] = *(const float4*)(xr + lane * 4 + j * 128);
        s  += v[j].x + v[j].y + v[j].z + v[j].w;
        s2 += v[j].x * v[j].x + v[j].y * v[j].y
            + v[j].z * v[j].z + v[j].w * v[j].w;
    }
    #pragma unroll
    for (int off = 16; off; off >>= 1) {
        s  += __shfl_xor_sync(0xffffffffu, s,  off);
        s2 += __shfl_xor_sync(0xffffffffu, s2, off);
    }
    const float mean = s * (1.0f / HDIM);
    const float var  = s2 * (1.0f / HDIM) - mean * mean;
    const float rs   = rsqrtf(var + 1e-5f);

    #pragma unroll
    for (int j = 0; j < 8; j++) {
        const int ci = lane * 4 + j * 128;
        const float4 gv = *(const float4*)(gamma + ci);
        const float4 bv = *(const float4*)(beta + ci);
        const float o0 = (v[j].x - mean) * rs * gv.x + bv.x;
        const float o1 = (v[j].y - mean) * rs * gv.y + bv.y;
        const float o2 = (v[j].z - mean) * rs * gv.z + bv.z;
        const float o3 = (v[j].w - mean) * rs * gv.w + bv.w;
        if (HALF_OUT) {
            __half2 h01 = __floats2half2_rn(o0, o1);
            __half2 h23 = __floats2half2_rn(o2, o3);
            uint2 pk;
            pk.x = *(uint32_t*)&h01;
            pk.y = *(uint32_t*)&h23;
            *(uint2*)((__half*)yv + (size_t)row * HDIM + ci) = pk;
        } else {
            *(float4*)((float*)yv + (size_t)row * HDIM + ci) =
                make_float4(o0, o1, o2, o3);
        }
    }
}

// ---------------------------------------------------------------------------
// Launch
// ---------------------------------------------------------------------------
extern "C" void kernel_launch(void* const* d_in, const int* in_sizes, int n_in,
                              void* d_out, int out_size) {
    const float* embeds = (const float*)d_in[0];
    const float* Wqkv  = (const float*)d_in[2];
    const float* bqkv  = (const float*)d_in[3];
    const float* Wo    = (const float*)d_in[4];
    const float* bo    = (const float*)d_in[5];
    const float* ln1g  = (const float*)d_in[6];
    const float* ln1b  = (const float*)d_in[7];
    const float* ln2g  = (const float*)d_in[8];
    const float* ln2b  = (const float*)d_in[9];
    const float* Wfc   = (const float*)d_in[10];
    const float* bfc   = (const float*)d_in[11];
    const float* Wproj = (const float*)d_in[12];
    const float* bproj = (const float*)d_in[13];
    const float* lnfg  = (const float*)d_in[14];
    const float* lnfb  = (const float*)d_in[15];

    float *h;
    __half *xh, *attnh, *fch, *qh, *kh, *vh, *Wqkvh, *Woh, *Wfch, *Wprojh;
    cudaGetSymbolAddress((void**)&h,      g_h);
    cudaGetSymbolAddress((void**)&xh,     g_xh);
    cudaGetSymbolAddress((void**)&attnh,  g_attnh);
    cudaGetSymbolAddress((void**)&fch,    g_fch);
    cudaGetSymbolAddress((void**)&qh,     g_qheads);
    cudaGetSymbolAddress((void**)&kh,     g_kheads);
    cudaGetSymbolAddress((void**)&vh,     g_vheads);
    cudaGetSymbolAddress((void**)&Wqkvh,  g_Wqkvh);
    cudaGetSymbolAddress((void**)&Woh,    g_Woh);
    cudaGetSymbolAddress((void**)&Wfch,   g_Wfch);
    cudaGetSymbolAddress((void**)&Wprojh, g_Wprojh);

    cudaFuncSetAttribute(mma_gemm<0>, cudaFuncAttributeMaxDynamicSharedMemorySize, GEMM_SMEM);
    cudaFuncSetAttribute(mma_gemm<1>, cudaFuncAttributeMaxDynamicSharedMemorySize, GEMM_SMEM);
    cudaFuncSetAttribute(mma_gemm<2>, cudaFuncAttributeMaxDynamicSharedMemorySize, GEMM_SMEM);
    cudaFuncSetAttribute(mma_gemm_qkv, cudaFuncAttributeMaxDynamicSharedMemorySize, GEMM_SMEM);
    cudaFuncSetAttribute(mma_attn,     cudaFuncAttributeMaxDynamicSharedMemorySize, ATTN_SMEM);

    convert_all<<<CONV_BLOCKS, 256>>>(Wqkv, Wo, Wfc, Wproj,
                                      Wqkvh, Woh, Wfch, Wprojh);

    for (int l = 0; l < NLAYER; l++) {
        const float* hin = (l == 0) ? embeds : h;
        ln_kernel<1><<<MTOK / 8, 256>>>(hin, ln1g + l * HDIM, ln1b + l * HDIM, xh);
        mma_gemm_qkv<<<dim3(3 * HDIM / 128, MTOK / 128), 256, GEMM_SMEM>>>(
            xh, Wqkvh + (size_t)l * HDIM * 3 * HDIM, bqkv + (size_t)l * 3 * HDIM,
            qh, kh, vh, HDIM);
        mma_attn<<<dim3(SEQ / 64, BATCH * NHEAD), 128, ATTN_SMEM>>>(qh, kh, vh, attnh);
        mma_gemm<1><<<dim3(HDIM / 128, MTOK / 128), 256, GEMM_SMEM>>>(
            attnh, Woh + (size_t)l * HDIM * HDIM, bo + (size_t)l * HDIM,
            hin, h, MTOK, HDIM, HDIM);
        ln_kernel<1><<<MTOK / 8, 256>>>(h, ln2g + l * HDIM, ln2b + l * HDIM, xh);
        mma_gemm<2><<<dim3(FFDIM / 128, MTOK / 128), 256, GEMM_SMEM>>>(
            xh, Wfch + (size_t)l * HDIM * FFDIM, bfc + (size_t)l * FFDIM,
            nullptr, fch, MTOK, FFDIM, HDIM);
        mma_gemm<1><<<dim3(HDIM / 128, MTOK / 128), 256, GEMM_SMEM>>>(
            fch, Wprojh + (size_t)l * FFDIM * HDIM, bproj + (size_t)l * HDIM,
            h, h, MTOK, HDIM, FFDIM);
    }
    ln_kernel<0><<<MTOK / 8, 256>>>(h, lnfg, lnfb, d_out);
}